// round 4
// baseline (speedup 1.0000x reference)
#include <cuda_runtime.h>
#include <math.h>
#include <stdint.h>

#define MAX_N 2048
#define MAX_E 32768
#define RFANf   0.14433756729740643f  // 1/sqrt(48)
#define RSQRT3f 0.57735026918962576f
#define RS32f   0.17677669529663687f  // 1/sqrt(32)

__device__ float d_q0g[MAX_N*32];
__device__ float d_q1g[MAX_N*48];
__device__ float d_v0e[(size_t)MAX_E*32];
__device__ float d_v1e[(size_t)MAX_E*48];
__device__ float d_logits[MAX_E*4];
__device__ float d_exb[MAX_E*4];
__device__ float d_segmax[MAX_N*4];
__device__ float d_denom[MAX_N*4];
__device__ float d_agg0[MAX_N*32];
__device__ float d_agg1[MAX_N*48];

__device__ __forceinline__ void atomicMaxF(float* a, float v){
  if (v >= 0.f) atomicMax((int*)a, __float_as_int(v));
  else atomicMin((unsigned int*)a, __float_as_uint(v));
}

__global__ void k_init(int N){
  int t = blockIdx.x*blockDim.x+threadIdx.x;
  if (t < N*4){ d_segmax[t] = -10.0f; d_denom[t] = 0.0f; }
  if (t < N*32) d_agg0[t] = 0.0f;
  if (t < N*48) d_agg1[t] = 0.0f;
}

__global__ void k_q(const float* __restrict__ nf, const float* __restrict__ Wq0,
                    const float* __restrict__ Wq1, int N){
  int t = blockIdx.x*blockDim.x+threadIdx.x;
  if (t >= N*80) return;
  int n = t/80, r = t - n*80;
  if (r < 32){
    int h = r>>3, w = r&7;
    const float* s = nf + (size_t)n*80;
    float acc = 0.f;
#pragma unroll
    for (int u = 0; u < 32; u++) acc += s[u]*Wq0[h*256+u*8+w];
    d_q0g[n*32+r] = acc*RS32f;
  } else {
    int rr = r-32, h = rr/12, q = rr - h*12, w = q/3, i = q - w*3;
    const float* v = nf + (size_t)n*80 + 32;
    float acc = 0.f;
#pragma unroll
    for (int u = 0; u < 16; u++) acc += v[u*3+i]*Wq1[h*64+u*4+w];
    d_q1g[n*48+rr] = acc*0.25f;
  }
}

// ---- smem layout (floats) ----
#define OFF_HT  0        // 2*64*64 = 8192
#define OFF_W2  8192     // 2*64*128 = 16384
#define OFF_WT  24576    // 64*132 = 8448 (also W1/b1 staging in setup)
#define WTP     132
#define OFF_O0  33024    // 2*64*32 = 4096
#define OFF_S1  37120    // 2*64*16 = 2048
#define OFF_V1  39168    // 2*64*48 = 6144
#define OFF_SS  45312    // 64*32
#define OFF_VV  47360    // 64*48
#define OFF_CVV 50432    // 64*16
#define OFF_SH  51456    // 64*4
#define OFF_EMB 51712    // 64*16
#define OFF_WD  52736    // 128
#define OFF_IDX 52864    // 128
#define SMEM_FLOATS 52992
#define SMEM_BYTES (SMEM_FLOATS*4)

__device__ __forceinline__ void cp16(float* dst, const float* src){
  uint32_t a = (uint32_t)__cvta_generic_to_shared(dst);
  asm volatile("cp.async.cg.shared.global [%0], [%1], 16;" :: "r"(a), "l"(src));
}
__device__ __forceinline__ unsigned long long dup2(float x){
  unsigned long long r; unsigned u = __float_as_uint(x);
  asm("mov.b64 %0, {%1, %1};" : "=l"(r) : "r"(u));
  return r;
}
__device__ __forceinline__ void fma2(unsigned long long& d, unsigned long long a, unsigned long long b){
  asm("fma.rn.f32x2 %0, %1, %2, %0;" : "+l"(d) : "l"(a), "l"(b));
}
__device__ __forceinline__ float lo2(unsigned long long x){ return __uint_as_float((unsigned)x); }
__device__ __forceinline__ float hi2(unsigned long long x){ return __uint_as_float((unsigned)(x>>32)); }

__global__ void __launch_bounds__(128,1) k_edge(
    const float* __restrict__ nf, const int* __restrict__ ei,
    const float* __restrict__ esh, const float* __restrict__ emb,
    const float* __restrict__ W1k, const float* __restrict__ b1k,
    const float* __restrict__ W2k, const float* __restrict__ b2k,
    const float* __restrict__ W1v, const float* __restrict__ b1v,
    const float* __restrict__ W2v, const float* __restrict__ b2v,
    const float* __restrict__ Wd0, const float* __restrict__ Wd1,
    int N, int E)
{
  extern __shared__ float sm[];
  float* sHT  = sm + OFF_HT;
  float* sW2  = sm + OFF_W2;
  float* sWT  = sm + OFF_WT;
  float* sO0  = sm + OFF_O0;
  float* sS1  = sm + OFF_S1;
  float* sV1  = sm + OFF_V1;
  float* sSS  = sm + OFF_SS;
  float* sVV  = sm + OFF_VV;
  float* sCVV = sm + OFF_CVV;
  float* sSH  = sm + OFF_SH;
  float* sEmb = sm + OFF_EMB;
  float* sWD  = sm + OFF_WD;
  int*   sIdx = (int*)(sm + OFF_IDX);

  const int t = threadIdx.x;
  const int eg0 = blockIdx.x*64;
  const int tx = t & 15, ty = t >> 4;

  // prefetch first W2 tile (set k, j0=0) into buffer 0
  {
    int col = (t & 31) << 2;
    int rb = t >> 5;
#pragma unroll
    for (int c = 0; c < 16; c++){
      int r = rb + (c<<2);
      cp16(sW2 + r*128 + col, W2k + (size_t)r*2304 + col);
    }
    asm volatile("cp.async.commit_group;");
  }

  {
    int e = t & 63, which = t >> 6;
    int eg = eg0 + e;
    sIdx[t] = (eg < E) ? ei[(size_t)which*E + eg] : 0;
  }
  for (int p = t; p < 256; p += 128){
    int e = p >> 2, c = p & 3;
    int eg = eg0 + e;
    bool val = eg < E;
    sSH[e*4+c] = val ? esh[(size_t)eg*4+c] : 0.f;
    float4 z = make_float4(0,0,0,0);
    float4 d = val ? *(const float4*)(emb + (size_t)eg*16 + c*4) : z;
    *(float4*)(sEmb + e*16 + c*4) = d;
  }
  for (int i = t; i < 1024; i += 128){ sWT[i] = W1k[i]; sWT[1024+i] = W1v[i]; }
  if (t < 64){ sWT[2048+t] = b1k[t]; sWT[2112+t] = b1v[t]; }
  if (t < 64) sWD[t] = Wd0[t];
  else if (t < 80) sWD[t] = Wd1[t-64];
  for (int i = t; i < 3072; i += 128) *(float4*)(sO0 + i*4) = make_float4(0,0,0,0);
  __syncthreads();

  // gather src node features: 2 threads per edge, 10 float4 each
  {
    int e = t >> 1, part = t & 1;
    const float4* row = (const float4*)(nf + (size_t)sIdx[e]*80);
#pragma unroll
    for (int q = 0; q < 10; q++){
      int f4 = part*10 + q;
      float4 d = row[f4];
      if (f4 < 8) *((float4*)(sSS + e*32) + f4) = d;
      else        *((float4*)(sVV + e*48) + (f4-8)) = d;
    }
  }
  __syncthreads();

  // cvv and hE (both sets)
  for (int i = t; i < 1024; i += 128){
    int e = i >> 4, u = i & 15;
    const float* vv = sVV + e*48 + u*3;
    sCVV[i] = (vv[0]*sSH[e*4+1] + vv[1]*sSH[e*4+2] + vv[2]*sSH[e*4+3]) * RSQRT3f;
  }
  {
    int e = t >> 1, kq = (t & 1) << 5;
#pragma unroll
    for (int s = 0; s < 2; s++){
      const float* W1s = sWT + s*1024;
      const float* b1s = sWT + 2048 + s*64;
      for (int kk = 0; kk < 32; kk++){
        int k = kq + kk;
        float acc = b1s[k];
#pragma unroll
        for (int b = 0; b < 16; b++) acc += sEmb[e*16+b]*W1s[b*64+k];
        sHT[s*4096 + k*64 + e] = acc/(1.f+expf(-acc));
      }
    }
  }
  __syncthreads();

  // ---------------- main loop: 36 tiles of 128 j (18 per set) ----------------
  for (int it = 0; it < 36; it++){
    int buf = it & 1;
    int s = (it >= 18) ? 1 : 0;
    int j0 = (it - s*18) << 7;

    if (it + 1 < 36){
      int s2 = ((it+1) >= 18) ? 1 : 0;
      int j02 = ((it+1) - s2*18) << 7;
      const float* W2n = s2 ? W2v : W2k;
      float* db = sW2 + (buf^1)*8192;
      int col = (t & 31) << 2;
      int rb = t >> 5;
#pragma unroll
      for (int c = 0; c < 16; c++){
        int r = rb + (c<<2);
        cp16(db + r*128 + col, W2n + (size_t)r*2304 + j02 + col);
      }
      asm volatile("cp.async.commit_group;");
      asm volatile("cp.async.wait_group 1;");
    } else {
      asm volatile("cp.async.wait_group 0;");
    }
    __syncthreads();   // W2[buf] ready; prior epilogue done with sWT

    // GEMM: 8 edges (4 f32x2 pairs) x 8 j per thread, init with bias
    unsigned long long acc[4][8];
    {
      const float* b2p = s ? b2v : b2k;
#pragma unroll
      for (int j = 0; j < 8; j++){
        unsigned long long bb = dup2(b2p[j0 + (tx<<3) + j]);
#pragma unroll
        for (int ep = 0; ep < 4; ep++) acc[ep][j] = bb;
      }
    }
    const float* aB = sHT + s*4096 + (ty<<3);
    const float* bB = sW2 + buf*8192 + (tx<<3);
#pragma unroll 4
    for (int k = 0; k < 64; k++){
      ulonglong2 a01 = *(const ulonglong2*)(aB + (k<<6));
      ulonglong2 a23 = *(const ulonglong2*)(aB + (k<<6) + 4);
      float4 bv0 = *(const float4*)(bB + (k<<7));
      float4 bv1 = *(const float4*)(bB + (k<<7) + 4);
      unsigned long long av[4];
      av[0]=a01.x; av[1]=a01.y; av[2]=a23.x; av[3]=a23.y;
      unsigned long long bd[8];
      bd[0]=dup2(bv0.x); bd[1]=dup2(bv0.y); bd[2]=dup2(bv0.z); bd[3]=dup2(bv0.w);
      bd[4]=dup2(bv1.x); bd[5]=dup2(bv1.y); bd[6]=dup2(bv1.z); bd[7]=dup2(bv1.w);
#pragma unroll
      for (int ep = 0; ep < 4; ep++)
#pragma unroll
        for (int j = 0; j < 8; j++)
          fma2(acc[ep][j], av[ep], bd[j]);
    }
    // stage w tile: [e][WTP]
#pragma unroll
    for (int ep = 0; ep < 4; ep++){
      int e = (ty<<3) + (ep<<1);
      float* w0 = sWT + e*WTP + (tx<<3);
      *(float4*)(w0)   = make_float4(lo2(acc[ep][0]),lo2(acc[ep][1]),lo2(acc[ep][2]),lo2(acc[ep][3]));
      *(float4*)(w0+4) = make_float4(lo2(acc[ep][4]),lo2(acc[ep][5]),lo2(acc[ep][6]),lo2(acc[ep][7]));
      float* w1r = w0 + WTP;
      *(float4*)(w1r)   = make_float4(hi2(acc[ep][0]),hi2(acc[ep][1]),hi2(acc[ep][2]),hi2(acc[ep][3]));
      *(float4*)(w1r+4) = make_float4(hi2(acc[ep][4]),hi2(acc[ep][5]),hi2(acc[ep][6]),hi2(acc[ep][7]));
    }
    __syncthreads();

    // epilogue: two 64-wide sub-blocks (region starts all = 0 mod 64)
#pragma unroll
    for (int sub = 0; sub < 2; sub++){
      int g = j0 + (sub<<6);
      int h = g/576, off0 = g - h*576;
      const float* wB = sWT + (sub<<6);
      if (off0 < 256){                     // ss -> out0 (coeff ss[u]*sh0)
        int u0 = off0 >> 3;
        for (int p = t; p < 512; p += 128){
          int e = p >> 3, ow = p & 7;
          const float* wr = wB + e*WTP + ow;
          float a = 0.f;
#pragma unroll
          for (int du = 0; du < 8; du++) a += sSS[e*32+u0+du]*wr[du*8];
          sO0[s*2048 + e*32 + h*8 + ow] += a*sSH[e*4];
        }
      } else if (off0 < 384){              // vv -> out0 (coeff cvv[u])
        int u0 = (off0-256) >> 3;
        for (int p = t; p < 512; p += 128){
          int e = p >> 3, ow = p & 7;
          const float* wr = wB + e*WTP + ow;
          float a = 0.f;
#pragma unroll
          for (int du = 0; du < 8; du++) a += sCVV[e*16+u0+du]*wr[du*8];
          sO0[s*2048 + e*32 + h*8 + ow] += a;
        }
      } else if (off0 < 512){              // sv -> s1 (coeff ss[u])
        int u0 = (off0-384) >> 2;
        for (int p = t; p < 256; p += 128){
          int e = p >> 2, w1 = p & 3;
          const float* wr = wB + e*WTP + w1;
          float a = 0.f;
#pragma unroll
          for (int du = 0; du < 16; du++) a += sSS[e*32+u0+du]*wr[du*4];
          sS1[s*1024 + e*16 + h*4 + w1] += a;
        }
      } else {                             // vs -> v1 (coeff vv[u,i]*sh0)
        for (int p = t; p < 768; p += 128){
          int e = p/12, r = p - e*12, w1 = r/3, i = r - w1*3;
          const float* wr = wB + e*WTP + w1;
          float a = 0.f;
#pragma unroll
          for (int du = 0; du < 16; du++) a += sVV[e*48+du*3+i]*wr[du*4];
          sV1[s*3072 + e*48 + h*12 + w1*3 + i] += a*sSH[e*4];
        }
      }
    }
  }
  __syncthreads();

  // write v-set outputs
  for (int p = t; p < 2048; p += 128){
    int e = p >> 5, c = p & 31;
    int eg = eg0 + e;
    if (eg < E) d_v0e[(size_t)eg*32 + c] = sO0[2048 + e*32 + c]*RFANf;
  }
  for (int p = t; p < 3072; p += 128){
    int e = p/48, r = p - e*48;
    int h = r/12, q = r - h*12, w1 = q/3, i = q - w1*3;
    int eg = eg0 + e;
    if (eg < E)
      d_v1e[(size_t)eg*48 + r] =
        (sS1[1024 + e*16 + h*4 + w1]*sSH[e*4+1+i] + sV1[3072 + e*48 + r])*RFANf;
  }

  // logits (k-set)
  for (int p = t; p < 256; p += 128){
    int e = p >> 2, h = p & 3;
    int eg = eg0 + e;
    int dst = sIdx[64 + e];
    float k0[8];
#pragma unroll
    for (int w = 0; w < 8; w++) k0[w] = sO0[e*32 + h*8 + w]*RFANf;
    const float* q0 = d_q0g + dst*32 + h*8;
    float l0 = 0.f;
#pragma unroll
    for (int v = 0; v < 8; v++){
      float tv = 0.f;
#pragma unroll
      for (int u = 0; u < 8; u++) tv += q0[u]*sWD[u*8+v];
      l0 += tv*k0[v];
    }
    float k1[12];
#pragma unroll
    for (int w1 = 0; w1 < 4; w1++)
#pragma unroll
      for (int i = 0; i < 3; i++)
        k1[w1*3+i] = (sS1[e*16+h*4+w1]*sSH[e*4+1+i] + sV1[e*48+h*12+w1*3+i])*RFANf;
    const float* q1 = d_q1g + dst*48 + h*12;
    float l1 = 0.f;
#pragma unroll
    for (int u = 0; u < 4; u++)
#pragma unroll
      for (int v = 0; v < 4; v++){
        float d3 = q1[u*3]*k1[v*3] + q1[u*3+1]*k1[v*3+1] + q1[u*3+2]*k1[v*3+2];
        l1 += sWD[64 + u*4 + v]*d3;
      }
    float lg = (l0 + l1*RSQRT3f)*0.025f;   // /sqrt(80)/sqrt(20)
    lg = fminf(fmaxf(lg, -10.f), 10.f);
    if (eg < E){
      d_logits[eg*4 + h] = lg;
      atomicMaxF(d_segmax + dst*4 + h, lg);
    }
  }
}

__global__ void k_ex(const int* __restrict__ ei, int E){
  int t = blockIdx.x*blockDim.x+threadIdx.x;
  if (t >= E*4) return;
  int e = t >> 2, h = t & 3;
  int dst = ei[E + e];
  float ex = expf(d_logits[t] - d_segmax[dst*4+h]);
  d_exb[t] = ex;
  atomicAdd(d_denom + dst*4 + h, ex);
}

__global__ void k_agg(const int* __restrict__ ei, int E){
  int t = blockIdx.x*blockDim.x+threadIdx.x;
  if (t >= E*80) return;
  int e = t/80, r = t - e*80;
  int dst = ei[E + e];
  if (r < 32){
    int h = r >> 3;
    float alpha = d_exb[e*4+h]/(d_denom[dst*4+h] + 1e-12f);
    atomicAdd(d_agg0 + dst*32 + r, alpha*d_v0e[(size_t)e*32 + r]);
  } else {
    int r2 = r - 32, h = r2/12;
    float alpha = d_exb[e*4+h]/(d_denom[dst*4+h] + 1e-12f);
    atomicAdd(d_agg1 + dst*48 + r2, alpha*d_v1e[(size_t)e*48 + r2]);
  }
}

__global__ void k_node(const float* __restrict__ nf,
    const float* __restrict__ Wo0, const float* __restrict__ Wo1,
    const float* __restrict__ Wf10, const float* __restrict__ Wf11,
    const float* __restrict__ Wf20, const float* __restrict__ Wf21,
    float* __restrict__ out, int N)
{
  __shared__ float sx0[32], sx1[48], sa0[64], sa1[48];
  int n = blockIdx.x, t = threadIdx.x;
  if (t < 32){
    float acc = 0.f;
#pragma unroll
    for (int u = 0; u < 32; u++) acc += d_agg0[n*32+u]*Wo0[u*32+t];
    sx0[t] = nf[(size_t)n*80 + t] + acc*RS32f;
  } else if (t < 80){
    int r = t-32, w = r/3, i = r - w*3;
    float acc = 0.f;
#pragma unroll
    for (int u = 0; u < 16; u++) acc += d_agg1[n*48+u*3+i]*Wo1[u*16+w];
    sx1[r] = nf[(size_t)n*80 + 32 + r] + acc*0.25f;
  }
  __syncthreads();
  if (t < 64){
    float acc = 0.f;
#pragma unroll
    for (int u = 0; u < 32; u++) acc += sx0[u]*Wf10[u*64+t];
    float a = acc*RS32f;
    sa0[t] = a/(1.f+expf(-a));
  } else if (t < 112){
    int r = t-64, w = r/3, i = r - w*3;
    float acc = 0.f;
#pragma unroll
    for (int u = 0; u < 16; u++) acc += sx1[u*3+i]*Wf11[u*16+w];
    sa1[r] = acc*0.25f;
  }
  __syncthreads();
  if (t < 16){
    float x = sa1[t*3], y = sa1[t*3+1], z = sa1[t*3+2];
    float nm = sqrtf(x*x+y*y+z*z);
    float g = (nm < 1e-8f) ? 0.f : (nm/(1.f+expf(-nm)))/nm;
    sa1[t*3] = x*g; sa1[t*3+1] = y*g; sa1[t*3+2] = z*g;
  }
  __syncthreads();
  if (t < 32){
    float acc = 0.f;
#pragma unroll
    for (int u = 0; u < 64; u++) acc += sa0[u]*Wf20[u*32+t];
    out[(size_t)n*80 + t] = sx0[t] + acc*0.125f;
  } else if (t < 80){
    int r = t-32, w = r/3, i = r - w*3;
    float acc = 0.f;
#pragma unroll
    for (int u = 0; u < 16; u++) acc += sa1[u*3+i]*Wf21[u*16+w];
    out[(size_t)n*80 + t] = sx1[r] + acc*0.25f;
  }
}

extern "C" void kernel_launch(void* const* d_in, const int* in_sizes, int n_in,
                              void* d_out, int out_size){
  const float* nf   = (const float*)d_in[0];
  const int*   ei   = (const int*)  d_in[1];
  const float* esh  = (const float*)d_in[2];
  const float* emb  = (const float*)d_in[3];
  const float* Wq0  = (const float*)d_in[4];
  const float* Wq1  = (const float*)d_in[5];
  const float* Wk1  = (const float*)d_in[6];
  const float* bk1  = (const float*)d_in[7];
  const float* Wk2  = (const float*)d_in[8];
  const float* bk2  = (const float*)d_in[9];
  const float* Wv1  = (const float*)d_in[10];
  const float* bv1  = (const float*)d_in[11];
  const float* Wv2  = (const float*)d_in[12];
  const float* bv2  = (const float*)d_in[13];
  const float* Wd0  = (const float*)d_in[14];
  const float* Wd1  = (const float*)d_in[15];
  const float* Wo0  = (const float*)d_in[16];
  const float* Wo1  = (const float*)d_in[17];
  const float* Wf10 = (const float*)d_in[18];
  const float* Wf11 = (const float*)d_in[19];
  const float* Wf20 = (const float*)d_in[20];
  const float* Wf21 = (const float*)d_in[21];
  float* out = (float*)d_out;

  int N = in_sizes[0]/80;
  int E = in_sizes[1]/2;

  static int smem_set = 0;
  if (!smem_set){
    cudaFuncSetAttribute(k_edge, cudaFuncAttributeMaxDynamicSharedMemorySize, SMEM_BYTES);
    smem_set = 1;
  }

  k_init<<<(N*48+255)/256, 256>>>(N);
  k_q<<<(N*80+255)/256, 256>>>(nf, Wq0, Wq1, N);
  k_edge<<<(E+63)/64, 128, SMEM_BYTES>>>(nf, ei, esh, emb,
      Wk1, bk1, Wk2, bk2, Wv1, bv1, Wv2, bv2, Wd0, Wd1, N, E);
  k_ex<<<(E*4+255)/256, 256>>>(ei, E);
  k_agg<<<(E*80+255)/256, 256>>>(ei, E);
  k_node<<<N, 128>>>(nf, Wo0, Wo1, Wf10, Wf11, Wf20, Wf21, out, N);
}

// round 5
// speedup vs baseline: 1.0184x; 1.0184x over previous
#include <cuda_runtime.h>
#include <math.h>
#include <stdint.h>

#define MAX_N 2048
#define MAX_E 32768
#define RFANf   0.14433756729740643f  // 1/sqrt(48)
#define RSQRT3f 0.57735026918962576f
#define RS32f   0.17677669529663687f  // 1/sqrt(32)

__device__ float d_q0g[MAX_N*32];
__device__ float d_q1g[MAX_N*48];
__device__ float d_v0e[(size_t)MAX_E*32];
__device__ float d_v1e[(size_t)MAX_E*48];
__device__ float d_logits[MAX_E*4];
__device__ float d_exb[MAX_E*4];
__device__ float d_segmax[MAX_N*4];
__device__ float d_denom[MAX_N*4];
__device__ float d_agg0[MAX_N*32];
__device__ float d_agg1[MAX_N*48];

__device__ __forceinline__ void atomicMaxF(float* a, float v){
  if (v >= 0.f) atomicMax((int*)a, __float_as_int(v));
  else atomicMin((unsigned int*)a, __float_as_uint(v));
}

__global__ void k_init(int N){
  int t = blockIdx.x*blockDim.x+threadIdx.x;
  if (t < N*4){ d_segmax[t] = -10.0f; d_denom[t] = 0.0f; }
  if (t < N*32) d_agg0[t] = 0.0f;
  if (t < N*48) d_agg1[t] = 0.0f;
}

__global__ void k_q(const float* __restrict__ nf, const float* __restrict__ Wq0,
                    const float* __restrict__ Wq1, int N){
  int t = blockIdx.x*blockDim.x+threadIdx.x;
  if (t >= N*80) return;
  int n = t/80, r = t - n*80;
  if (r < 32){
    int h = r>>3, w = r&7;
    const float* s = nf + (size_t)n*80;
    float acc = 0.f;
#pragma unroll
    for (int u = 0; u < 32; u++) acc += s[u]*Wq0[h*256+u*8+w];
    d_q0g[n*32+r] = acc*RS32f;
  } else {
    int rr = r-32, h = rr/12, q = rr - h*12, w = q/3, i = q - w*3;
    const float* v = nf + (size_t)n*80 + 32;
    float acc = 0.f;
#pragma unroll
    for (int u = 0; u < 16; u++) acc += v[u*3+i]*Wq1[h*64+u*4+w];
    d_q1g[n*48+rr] = acc*0.25f;
  }
}

// ---- smem layout (floats) ----
#define OFF_HT   0        // 2*64*64 = 8192
#define OFF_W2   8192     // 2 bufs * 8320 (32 jg * 260) = 16640
#define W2BUF    8320
#define OFF_WT   24832    // 64*132 = 8448
#define WTP      132
#define OFF_O0   33280    // 2*64*32 = 4096
#define OFF_S1   37376    // 2*64*16 = 2048
#define OFF_V1   39424    // 2*64*48 = 6144
#define OFF_SS   45568    // 64*32
#define OFF_VV   47616    // 64*48
#define OFF_CVV  50688    // 64*16
#define OFF_SH   51712    // 64*4
#define OFF_EMB  51968    // 64*16
#define OFF_WD   52992    // 128
#define OFF_IDX  53120    // 128
#define OFF_W1   53248    // 2048 + 128
#define SMEM_FLOATS 55424
#define SMEM_BYTES (SMEM_FLOATS*4)   // 221696 B

__device__ __forceinline__ void cp16(float* dst, const float* src){
  uint32_t a = (uint32_t)__cvta_generic_to_shared(dst);
  asm volatile("cp.async.cg.shared.global [%0], [%1], 16;" :: "r"(a), "l"(src));
}
__device__ __forceinline__ unsigned long long dup2(float x){
  unsigned long long r; unsigned u = __float_as_uint(x);
  asm("mov.b64 %0, {%1, %1};" : "=l"(r) : "r"(u));
  return r;
}
__device__ __forceinline__ void fma2(unsigned long long& d, unsigned long long a, unsigned long long b){
  asm("fma.rn.f32x2 %0, %1, %2, %0;" : "+l"(d) : "l"(a), "l"(b));
}
__device__ __forceinline__ float lo2(unsigned long long x){ return __uint_as_float((unsigned)x); }
__device__ __forceinline__ float hi2(unsigned long long x){ return __uint_as_float((unsigned)(x>>32)); }

__global__ void __launch_bounds__(256,1) k_edge(
    const float* __restrict__ nf, const int* __restrict__ ei,
    const float* __restrict__ esh, const float* __restrict__ emb,
    const float* __restrict__ W1k, const float* __restrict__ b1k,
    const float* __restrict__ W2k, const float* __restrict__ b2k,
    const float* __restrict__ W1v, const float* __restrict__ b1v,
    const float* __restrict__ W2v, const float* __restrict__ b2v,
    const float* __restrict__ Wd0, const float* __restrict__ Wd1,
    int N, int E)
{
  extern __shared__ float sm[];
  float* sHT  = sm + OFF_HT;
  float* sW2  = sm + OFF_W2;
  float* sWT  = sm + OFF_WT;
  float* sO0  = sm + OFF_O0;
  float* sS1  = sm + OFF_S1;
  float* sV1  = sm + OFF_V1;
  float* sSS  = sm + OFF_SS;
  float* sVV  = sm + OFF_VV;
  float* sCVV = sm + OFF_CVV;
  float* sSH  = sm + OFF_SH;
  float* sEmb = sm + OFF_EMB;
  float* sWD  = sm + OFF_WD;
  int*   sIdx = (int*)(sm + OFF_IDX);
  float* sW1  = sm + OFF_W1;

  const int t  = threadIdx.x;
  const int tx = t & 31, ty = t >> 5;
  const int nT = (E + 63) >> 6;

  // one-time staging
  for (int i = t; i < 1024; i += 256){ sW1[i] = W1k[i]; sW1[1024+i] = W1v[i]; }
  if (t < 64){ sW1[2048+t] = b1k[t]; sW1[2112+t] = b1v[t]; }
  if (t < 64) sWD[t] = Wd0[t];
  else if (t < 80) sWD[t] = Wd1[t-64];

  for (int et = blockIdx.x; et < nT; et += gridDim.x){
    const int eg0 = et << 6;
    __syncthreads();   // all prior readers of smem done

    // prefetch chunk 0 (set k, j0=0, k0=0) into buf 0, transposed layout [jg][kk][8]
    {
#pragma unroll
      for (int c = 0; c < 4; c++){
        int kk = ty + (c<<3);
        float* d = sW2 + tx*260 + kk*8;
        const float* srcp = W2k + (size_t)kk*2304 + tx*8;
        cp16(d, srcp); cp16(d+4, srcp+4);
      }
      asm volatile("cp.async.commit_group;");
    }

    if (t < 128){
      int e = t & 63, which = t >> 6;
      int eg = eg0 + e;
      sIdx[t] = (eg < E) ? ei[(size_t)which*E + eg] : 0;
    }
    {
      int e = t >> 2, c = t & 3;
      int eg = eg0 + e;
      bool val = eg < E;
      sSH[e*4+c] = val ? esh[(size_t)eg*4+c] : 0.f;
      float4 z = make_float4(0,0,0,0);
      float4 d = val ? *(const float4*)(emb + (size_t)eg*16 + c*4) : z;
      *(float4*)(sEmb + e*16 + c*4) = d;
    }
    for (int i = t; i < 3072; i += 256) *(float4*)(sO0 + i*4) = make_float4(0,0,0,0);
    __syncthreads();   // sIdx ready

    // gather src node features
    {
      int e = t >> 2, part = t & 3;
      const float4* row = (const float4*)(nf + (size_t)sIdx[e]*80);
#pragma unroll
      for (int q = 0; q < 5; q++){
        int f4 = part*5 + q;
        float4 d = row[f4];
        if (f4 < 8) *((float4*)(sSS + e*32) + f4) = d;
        else        *((float4*)(sVV + e*48) + (f4-8)) = d;
      }
    }
    __syncthreads();

    // cvv
    for (int i = t; i < 1024; i += 256){
      int e = i >> 4, u = i & 15;
      const float* vv = sVV + e*48 + u*3;
      sCVV[i] = (vv[0]*sSH[e*4+1] + vv[1]*sSH[e*4+2] + vv[2]*sSH[e*4+3]) * RSQRT3f;
    }
    // hE (both sets), layout [s][k][e]
    {
      int e = t >> 2, kq = (t & 3) << 4;
#pragma unroll
      for (int s = 0; s < 2; s++){
        const float* W1s = sW1 + s*1024;
        const float* b1s = sW1 + 2048 + s*64;
        for (int kk = 0; kk < 16; kk++){
          int k = kq + kk;
          float a = b1s[k];
#pragma unroll
          for (int b = 0; b < 16; b++) a += sEmb[e*16+b]*W1s[b*64+k];
          sHT[s*4096 + k*64 + e] = a/(1.f+expf(-a));
        }
      }
    }
    __syncthreads();

    // ---- main loop: 36 chunks = 18 j-tiles (256 j) x 2 k-chunks (32 k) ----
    unsigned long long acc[4][8];
    for (int cc = 0; cc < 36; cc++){
      int buf = cc & 1;
      int it = cc >> 1, kc = cc & 1;
      int s  = (it >= 9) ? 1 : 0;
      int j0 = (it - s*9) << 8;
      int k0 = kc << 5;

      if (cc + 1 < 36){
        int it2 = (cc+1) >> 1, kc2 = (cc+1) & 1;
        int s2  = (it2 >= 9) ? 1 : 0;
        int j02 = (it2 - s2*9) << 8;
        int k02 = kc2 << 5;
        const float* W2s = s2 ? W2v : W2k;
        float* db = sW2 + (buf^1)*W2BUF;
#pragma unroll
        for (int c = 0; c < 4; c++){
          int kk = ty + (c<<3);
          float* d = db + tx*260 + kk*8;
          const float* srcp = W2s + (size_t)(k02+kk)*2304 + j02 + tx*8;
          cp16(d, srcp); cp16(d+4, srcp+4);
        }
        asm volatile("cp.async.commit_group;");
        asm volatile("cp.async.wait_group 1;");
      } else {
        asm volatile("cp.async.wait_group 0;");
      }
      __syncthreads();   // W2[buf] visible to all

      if (kc == 0){
        const float* b2p = s ? b2v : b2k;
#pragma unroll
        for (int j = 0; j < 8; j++){
          unsigned long long bb = dup2(b2p[j0 + (tx<<3) + j]);
#pragma unroll
          for (int ep = 0; ep < 4; ep++) acc[ep][j] = bb;
        }
      }
      const float* aB = sHT + s*4096 + (k0<<6) + (ty<<3);
      const float* bB = sW2 + buf*W2BUF + tx*260;
#pragma unroll 4
      for (int kk = 0; kk < 32; kk++){
        ulonglong2 a01 = *(const ulonglong2*)(aB + (kk<<6));
        ulonglong2 a23 = *(const ulonglong2*)(aB + (kk<<6) + 4);
        float4 bv0 = *(const float4*)(bB + (kk<<3));
        float4 bv1 = *(const float4*)(bB + (kk<<3) + 4);
        unsigned long long av0 = a01.x, av1 = a01.y, av2 = a23.x, av3 = a23.y;
        unsigned long long bd[8];
        bd[0]=dup2(bv0.x); bd[1]=dup2(bv0.y); bd[2]=dup2(bv0.z); bd[3]=dup2(bv0.w);
        bd[4]=dup2(bv1.x); bd[5]=dup2(bv1.y); bd[6]=dup2(bv1.z); bd[7]=dup2(bv1.w);
#pragma unroll
        for (int j = 0; j < 8; j++){
          fma2(acc[0][j], av0, bd[j]);
          fma2(acc[1][j], av1, bd[j]);
          fma2(acc[2][j], av2, bd[j]);
          fma2(acc[3][j], av3, bd[j]);
        }
      }

      if (kc == 1){
        // epilogue: two 128-j halves (stage -> contract)
#pragma unroll
        for (int h2 = 0; h2 < 2; h2++){
          if ((tx >> 4) == h2){
            int jc = (tx & 15) << 3;
#pragma unroll
            for (int ep = 0; ep < 4; ep++){
              int e = (ty<<3) + (ep<<1);
              float* w0 = sWT + e*WTP + jc;
              *(float4*)(w0)   = make_float4(lo2(acc[ep][0]),lo2(acc[ep][1]),lo2(acc[ep][2]),lo2(acc[ep][3]));
              *(float4*)(w0+4) = make_float4(lo2(acc[ep][4]),lo2(acc[ep][5]),lo2(acc[ep][6]),lo2(acc[ep][7]));
              float* w1r = w0 + WTP;
              *(float4*)(w1r)   = make_float4(hi2(acc[ep][0]),hi2(acc[ep][1]),hi2(acc[ep][2]),hi2(acc[ep][3]));
              *(float4*)(w1r+4) = make_float4(hi2(acc[ep][4]),hi2(acc[ep][5]),hi2(acc[ep][6]),hi2(acc[ep][7]));
            }
          }
          __syncthreads();
#pragma unroll
          for (int sb = 0; sb < 2; sb++){
            int g = j0 + (h2<<7) + (sb<<6);
            int h = g/576, off0 = g - h*576;
            const float* wB = sWT + (sb<<6);
            if (off0 < 256){                     // ss -> out0 (coeff ss[u]*sh0)
              int u0 = off0 >> 3;
              for (int p = t; p < 512; p += 256){
                int e = p >> 3, ow = p & 7;
                const float* wr = wB + e*WTP + ow;
                float a = 0.f;
#pragma unroll
                for (int du = 0; du < 8; du++) a += sSS[e*32+u0+du]*wr[du*8];
                sO0[s*2048 + e*32 + h*8 + ow] += a*sSH[e*4];
              }
            } else if (off0 < 384){              // vv -> out0 (coeff cvv[u])
              int u0 = (off0-256) >> 3;
              for (int p = t; p < 512; p += 256){
                int e = p >> 3, ow = p & 7;
                const float* wr = wB + e*WTP + ow;
                float a = 0.f;
#pragma unroll
                for (int du = 0; du < 8; du++) a += sCVV[e*16+u0+du]*wr[du*8];
                sO0[s*2048 + e*32 + h*8 + ow] += a;
              }
            } else if (off0 < 512){              // sv -> s1 (coeff ss[u])
              int u0 = (off0-384) >> 2;
              {
                int e = t >> 2, w1 = t & 3;
                const float* wr = wB + e*WTP + w1;
                float a = 0.f;
#pragma unroll
                for (int du = 0; du < 16; du++) a += sSS[e*32+u0+du]*wr[du*4];
                sS1[s*1024 + e*16 + h*4 + w1] += a;
              }
            } else {                             // vs -> v1 (coeff vv[u,i]*sh0)
              for (int p = t; p < 768; p += 256){
                int e = p/12, r = p - e*12, w1 = r/3, i = r - w1*3;
                const float* wr = wB + e*WTP + w1;
                float a = 0.f;
#pragma unroll
                for (int du = 0; du < 16; du++) a += sVV[e*48+du*3+i]*wr[du*4];
                sV1[s*3072 + e*48 + h*12 + w1*3 + i] += a*sSH[e*4];
              }
            }
          }
          __syncthreads();
        }
      } else {
        __syncthreads();   // protect buf^1 before next prefetch
      }
    }

    // write v-set outputs
    for (int p = t; p < 2048; p += 256){
      int e = p >> 5, c = p & 31;
      int eg = eg0 + e;
      if (eg < E) d_v0e[(size_t)eg*32 + c] = sO0[2048 + e*32 + c]*RFANf;
    }
    for (int p = t; p < 3072; p += 256){
      int e = p/48, r = p - e*48;
      int h = r/12, q = r - h*12, w1 = q/3, i = q - w1*3;
      int eg = eg0 + e;
      if (eg < E)
        d_v1e[(size_t)eg*48 + r] =
          (sS1[1024 + e*16 + h*4 + w1]*sSH[e*4+1+i] + sV1[3072 + e*48 + r])*RFANf;
    }

    // logits (k-set)
    {
      int e = t >> 2, h = t & 3;
      int eg = eg0 + e;
      int dst = sIdx[64 + e];
      float k0r[8];
#pragma unroll
      for (int w = 0; w < 8; w++) k0r[w] = sO0[e*32 + h*8 + w]*RFANf;
      const float* q0 = d_q0g + dst*32 + h*8;
      float l0 = 0.f;
#pragma unroll
      for (int v = 0; v < 8; v++){
        float tv = 0.f;
#pragma unroll
        for (int u = 0; u < 8; u++) tv += q0[u]*sWD[u*8+v];
        l0 += tv*k0r[v];
      }
      float k1r[12];
#pragma unroll
      for (int w1 = 0; w1 < 4; w1++)
#pragma unroll
        for (int i = 0; i < 3; i++)
          k1r[w1*3+i] = (sS1[e*16+h*4+w1]*sSH[e*4+1+i] + sV1[e*48+h*12+w1*3+i])*RFANf;
      const float* q1 = d_q1g + dst*48 + h*12;
      float l1 = 0.f;
#pragma unroll
      for (int u = 0; u < 4; u++)
#pragma unroll
        for (int v = 0; v < 4; v++){
          float d3 = q1[u*3]*k1r[v*3] + q1[u*3+1]*k1r[v*3+1] + q1[u*3+2]*k1r[v*3+2];
          l1 += sWD[64 + u*4 + v]*d3;
        }
      float lg = (l0 + l1*RSQRT3f)*0.025f;
      lg = fminf(fmaxf(lg, -10.f), 10.f);
      if (eg < E){
        d_logits[eg*4 + h] = lg;
        atomicMaxF(d_segmax + dst*4 + h, lg);
      }
    }
  }
}

__global__ void k_ex(const int* __restrict__ ei, int E){
  int t = blockIdx.x*blockDim.x+threadIdx.x;
  if (t >= E*4) return;
  int e = t >> 2, h = t & 3;
  int dst = ei[E + e];
  float ex = expf(d_logits[t] - d_segmax[dst*4+h]);
  d_exb[t] = ex;
  atomicAdd(d_denom + dst*4 + h, ex);
}

__global__ void k_agg(const int* __restrict__ ei, int E){
  int t = blockIdx.x*blockDim.x+threadIdx.x;
  if (t >= E*80) return;
  int e = t/80, r = t - e*80;
  int dst = ei[E + e];
  if (r < 32){
    int h = r >> 3;
    float alpha = d_exb[e*4+h]/(d_denom[dst*4+h] + 1e-12f);
    atomicAdd(d_agg0 + dst*32 + r, alpha*d_v0e[(size_t)e*32 + r]);
  } else {
    int r2 = r - 32, h = r2/12;
    float alpha = d_exb[e*4+h]/(d_denom[dst*4+h] + 1e-12f);
    atomicAdd(d_agg1 + dst*48 + r2, alpha*d_v1e[(size_t)e*48 + r2]);
  }
}

__global__ void k_node(const float* __restrict__ nf,
    const float* __restrict__ Wo0, const float* __restrict__ Wo1,
    const float* __restrict__ Wf10, const float* __restrict__ Wf11,
    const float* __restrict__ Wf20, const float* __restrict__ Wf21,
    float* __restrict__ out, int N)
{
  __shared__ float sx0[32], sx1[48], sa0[64], sa1[48];
  int n = blockIdx.x, t = threadIdx.x;
  if (t < 32){
    float acc = 0.f;
#pragma unroll
    for (int u = 0; u < 32; u++) acc += d_agg0[n*32+u]*Wo0[u*32+t];
    sx0[t] = nf[(size_t)n*80 + t] + acc*RS32f;
  } else if (t < 80){
    int r = t-32, w = r/3, i = r - w*3;
    float acc = 0.f;
#pragma unroll
    for (int u = 0; u < 16; u++) acc += d_agg1[n*48+u*3+i]*Wo1[u*16+w];
    sx1[r] = nf[(size_t)n*80 + 32 + r] + acc*0.25f;
  }
  __syncthreads();
  if (t < 64){
    float acc = 0.f;
#pragma unroll
    for (int u = 0; u < 32; u++) acc += sx0[u]*Wf10[u*64+t];
    float a = acc*RS32f;
    sa0[t] = a/(1.f+expf(-a));
  } else if (t < 112){
    int r = t-64, w = r/3, i = r - w*3;
    float acc = 0.f;
#pragma unroll
    for (int u = 0; u < 16; u++) acc += sx1[u*3+i]*Wf11[u*16+w];
    sa1[r] = acc*0.25f;
  }
  __syncthreads();
  if (t < 16){
    float x = sa1[t*3], y = sa1[t*3+1], z = sa1[t*3+2];
    float nm = sqrtf(x*x+y*y+z*z);
    float g = (nm < 1e-8f) ? 0.f : (nm/(1.f+expf(-nm)))/nm;
    sa1[t*3] = x*g; sa1[t*3+1] = y*g; sa1[t*3+2] = z*g;
  }
  __syncthreads();
  if (t < 32){
    float acc = 0.f;
#pragma unroll
    for (int u = 0; u < 64; u++) acc += sa0[u]*Wf20[u*32+t];
    out[(size_t)n*80 + t] = sx0[t] + acc*0.125f;
  } else if (t < 80){
    int r = t-32, w = r/3, i = r - w*3;
    float acc = 0.f;
#pragma unroll
    for (int u = 0; u < 16; u++) acc += sa1[u*3+i]*Wf21[u*16+w];
    out[(size_t)n*80 + t] = sx1[r] + acc*0.25f;
  }
}

extern "C" void kernel_launch(void* const* d_in, const int* in_sizes, int n_in,
                              void* d_out, int out_size){
  const float* nf   = (const float*)d_in[0];
  const int*   ei   = (const int*)  d_in[1];
  const float* esh  = (const float*)d_in[2];
  const float* emb  = (const float*)d_in[3];
  const float* Wq0  = (const float*)d_in[4];
  const float* Wq1  = (const float*)d_in[5];
  const float* Wk1  = (const float*)d_in[6];
  const float* bk1  = (const float*)d_in[7];
  const float* Wk2  = (const float*)d_in[8];
  const float* bk2  = (const float*)d_in[9];
  const float* Wv1  = (const float*)d_in[10];
  const float* bv1  = (const float*)d_in[11];
  const float* Wv2  = (const float*)d_in[12];
  const float* bv2  = (const float*)d_in[13];
  const float* Wd0  = (const float*)d_in[14];
  const float* Wd1  = (const float*)d_in[15];
  const float* Wo0  = (const float*)d_in[16];
  const float* Wo1  = (const float*)d_in[17];
  const float* Wf10 = (const float*)d_in[18];
  const float* Wf11 = (const float*)d_in[19];
  const float* Wf20 = (const float*)d_in[20];
  const float* Wf21 = (const float*)d_in[21];
  float* out = (float*)d_out;

  int N = in_sizes[0]/80;
  int E = in_sizes[1]/2;

  static int smCount = 0;
  if (!smCount){
    cudaFuncSetAttribute(k_edge, cudaFuncAttributeMaxDynamicSharedMemorySize, SMEM_BYTES);
    cudaDeviceGetAttribute(&smCount, cudaDevAttrMultiProcessorCount, 0);
    if (smCount <= 0) smCount = 148;
  }
  int nT = (E + 63)/64;
  int grid = nT < smCount ? nT : smCount;

  k_init<<<(N*48+255)/256, 256>>>(N);
  k_q<<<(N*80+255)/256, 256>>>(nf, Wq0, Wq1, N);
  k_edge<<<grid, 256, SMEM_BYTES>>>(nf, ei, esh, emb,
      Wk1, bk1, Wk2, bk2, Wv1, bv1, Wv2, bv2, Wd0, Wd1, N, E);
  k_ex<<<(E*4+255)/256, 256>>>(ei, E);
  k_agg<<<(E*80+255)/256, 256>>>(ei, E);
  k_node<<<N, 128>>>(nf, Wo0, Wo1, Wf10, Wf11, Wf20, Wf21, out, N);
}

// round 6
// speedup vs baseline: 1.4350x; 1.4090x over previous
#include <cuda_runtime.h>
#include <cuda_bf16.h>
#include <math.h>
#include <stdint.h>

#define MAX_N 2048
#define MAX_E 32768
#define RFANf   0.14433756729740643f  // 1/sqrt(48)
#define RSQRT3f 0.57735026918962576f
#define RS32f   0.17677669529663687f  // 1/sqrt(32)

__device__ float d_q0g[MAX_N*32];
__device__ float d_q1g[MAX_N*48];
__device__ float d_v0e[(size_t)MAX_E*32];
__device__ float d_v1e[(size_t)MAX_E*48];
__device__ float d_logits[MAX_E*4];
__device__ float d_exb[MAX_E*4];
__device__ float d_segmax[MAX_N*4];
__device__ float d_denom[MAX_N*4];
__device__ float d_agg0[MAX_N*32];
__device__ float d_agg1[MAX_N*48];
// W2 as bf16 hi/lo, k-pair interleaved: row r = set*64 + part*32 + kp (kp=k/2),
// word = (hi16(k=2kp+1)<<16)|hi16(k=2kp), 2304 words per row.
__device__ unsigned int d_W2p[128*2304];

__device__ __forceinline__ void atomicMaxF(float* a, float v){
  if (v >= 0.f) atomicMax((int*)a, __float_as_int(v));
  else atomicMin((unsigned int*)a, __float_as_uint(v));
}

__device__ __forceinline__ unsigned packbf(float x, float y){
  unsigned short ux = __bfloat16_as_ushort(__float2bfloat16(x));
  unsigned short uy = __bfloat16_as_ushort(__float2bfloat16(y));
  return ((unsigned)uy << 16) | (unsigned)ux;
}

// -------- prep: split W2 into bf16 hi/lo pairs --------
__global__ void k_prep(const float* __restrict__ W2k, const float* __restrict__ W2v){
  int t = blockIdx.x*blockDim.x + threadIdx.x;
  if (t >= 2*32*2304) return;
  int s  = t / (32*2304);
  int r  = t - s*32*2304;
  int kp = r / 2304;
  int j  = r - kp*2304;
  const float* W = s ? W2v : W2k;
  float a0 = W[(2*kp)*2304 + j];
  float a1 = W[(2*kp+1)*2304 + j];
  __nv_bfloat16 h0 = __float2bfloat16(a0);
  __nv_bfloat16 h1 = __float2bfloat16(a1);
  float l0 = a0 - __bfloat162float(h0);
  float l1 = a1 - __bfloat162float(h1);
  d_W2p[(size_t)(s*64 + kp)*2304 + j]      = ((unsigned)__bfloat16_as_ushort(h1)<<16) | __bfloat16_as_ushort(h0);
  d_W2p[(size_t)(s*64 + 32 + kp)*2304 + j] = packbf(l0, l1);
}

__global__ void k_init(int N){
  int t = blockIdx.x*blockDim.x+threadIdx.x;
  if (t < N*4){ d_segmax[t] = -10.0f; d_denom[t] = 0.0f; }
  if (t < N*32) d_agg0[t] = 0.0f;
  if (t < N*48) d_agg1[t] = 0.0f;
}

__global__ void k_q(const float* __restrict__ nf, const float* __restrict__ Wq0,
                    const float* __restrict__ Wq1, int N){
  int t = blockIdx.x*blockDim.x+threadIdx.x;
  if (t >= N*80) return;
  int n = t/80, r = t - n*80;
  if (r < 32){
    int h = r>>3, w = r&7;
    const float* s = nf + (size_t)n*80;
    float acc = 0.f;
#pragma unroll
    for (int u = 0; u < 32; u++) acc += s[u]*Wq0[h*256+u*8+w];
    d_q0g[n*32+r] = acc*RS32f;
  } else {
    int rr = r-32, h = rr/12, q = rr - h*12, w = q/3, i = q - w*3;
    const float* v = nf + (size_t)n*80 + 32;
    float acc = 0.f;
#pragma unroll
    for (int u = 0; u < 16; u++) acc += v[u*3+i]*Wq1[h*64+u*4+w];
    d_q1g[n*48+rr] = acc*0.25f;
  }
}

// ---- smem layout (32-bit words) ----
#define OFF_A    0        // 2 sets * 64e * 68 = 8704 (bf16 pairs: hi kp0..31, lo 32..63)
#define ARS      68
#define OFF_B    8704     // 2 bufs * 64 rows * 136 = 17408
#define BRS      136
#define BBUF     8704
#define OFF_WT   26112    // 64*132 = 8448 (w staging fp32)
#define WTP      132
#define OFF_O0   34560    // 2*64*32 = 4096
#define OFF_S1   38656    // 2*64*16 = 2048
#define OFF_V1   40704    // 2*64*48 = 6144
#define OFF_SS   46848    // 64*32
#define OFF_VV   48896    // 64*48
#define OFF_CVV  51968    // 64*16
#define OFF_SH   52992    // 64*4
#define OFF_EMB  53248    // 64*16
#define OFF_WD   54272    // 128
#define OFF_IDX  54400    // 128
#define OFF_W1   54528    // 2176
#define SMEM_WORDS 56704
#define SMEM_BYTES (SMEM_WORDS*4)   // 226816

__device__ __forceinline__ void cp16(void* dst, const void* src){
  uint32_t a = (uint32_t)__cvta_generic_to_shared(dst);
  asm volatile("cp.async.cg.shared.global [%0], [%1], 16;" :: "r"(a), "l"(src));
}

__device__ __forceinline__ void mma_bf16(float& c0, float& c1, float& c2, float& c3,
                                         unsigned a0, unsigned a1, unsigned b0){
  asm volatile(
    "mma.sync.aligned.m16n8k8.row.col.f32.bf16.bf16.f32 "
    "{%0,%1,%2,%3},{%4,%5},{%6},{%0,%1,%2,%3};"
    : "+f"(c0), "+f"(c1), "+f"(c2), "+f"(c3)
    : "r"(a0), "r"(a1), "r"(b0));
}

__global__ void __launch_bounds__(256,1) k_edge(
    const float* __restrict__ nf, const int* __restrict__ ei,
    const float* __restrict__ esh, const float* __restrict__ emb,
    const float* __restrict__ W1k, const float* __restrict__ b1k,
    const float* __restrict__ b2k,
    const float* __restrict__ W1v, const float* __restrict__ b1v,
    const float* __restrict__ b2v,
    const float* __restrict__ Wd0, const float* __restrict__ Wd1,
    int N, int E)
{
  extern __shared__ float sm[];
  unsigned* sA  = (unsigned*)(sm + OFF_A);
  unsigned* sB  = (unsigned*)(sm + OFF_B);
  float* sWT  = sm + OFF_WT;
  float* sO0  = sm + OFF_O0;
  float* sS1  = sm + OFF_S1;
  float* sV1  = sm + OFF_V1;
  float* sSS  = sm + OFF_SS;
  float* sVV  = sm + OFF_VV;
  float* sCVV = sm + OFF_CVV;
  float* sSH  = sm + OFF_SH;
  float* sEmb = sm + OFF_EMB;
  float* sWD  = sm + OFF_WD;
  int*   sIdx = (int*)(sm + OFF_IDX);
  float* sW1  = sm + OFF_W1;

  const int t    = threadIdx.x;
  const int lane = t & 31;
  const int wid  = t >> 5;
  const int wm   = wid >> 1, wn = wid & 1;
  const int g    = lane >> 2, c = lane & 3;
  const int e0   = wm << 4;
  const int nT = (E + 63) >> 6;

  // one-time staging
  for (int i = t; i < 1024; i += 256){ sW1[i] = W1k[i]; sW1[1024+i] = W1v[i]; }
  if (t < 64){ sW1[2048+t] = b1k[t]; sW1[2112+t] = b1v[t]; }
  if (t < 64) sWD[t] = Wd0[t];
  else if (t < 80) sWD[t] = Wd1[t-64];

  for (int et = blockIdx.x; et < nT; et += gridDim.x){
    const int eg0 = et << 6;
    __syncthreads();

    // prefetch B tile 0 (set 0, j0=0) into buf 0
    {
      int colw = (t & 31) << 2;
      int rb = t >> 5;
#pragma unroll
      for (int q = 0; q < 8; q++){
        int r = rb + (q<<3);
        cp16(sB + r*BRS + colw, d_W2p + (size_t)r*2304 + colw);
      }
      asm volatile("cp.async.commit_group;");
    }

    if (t < 128){
      int e = t & 63, which = t >> 6;
      int eg = eg0 + e;
      sIdx[t] = (eg < E) ? ei[(size_t)which*E + eg] : 0;
    }
    {
      int e = t >> 2, cc = t & 3;
      int eg = eg0 + e;
      bool val = eg < E;
      sSH[e*4+cc] = val ? esh[(size_t)eg*4+cc] : 0.f;
      float4 z = make_float4(0,0,0,0);
      float4 d = val ? *(const float4*)(emb + (size_t)eg*16 + cc*4) : z;
      *(float4*)(sEmb + e*16 + cc*4) = d;
    }
    for (int i = t; i < 3072; i += 256) *(float4*)(sO0 + i*4) = make_float4(0,0,0,0);
    __syncthreads();

    // gather src node features
    {
      int e = t >> 2, part = t & 3;
      const float4* row = (const float4*)(nf + (size_t)sIdx[e]*80);
#pragma unroll
      for (int q = 0; q < 5; q++){
        int f4 = part*5 + q;
        float4 d = row[f4];
        if (f4 < 8) *((float4*)(sSS + e*32) + f4) = d;
        else        *((float4*)(sVV + e*48) + (f4-8)) = d;
      }
    }
    __syncthreads();

    // cvv
    for (int i = t; i < 1024; i += 256){
      int e = i >> 4, u = i & 15;
      const float* vv = sVV + e*48 + u*3;
      sCVV[i] = (vv[0]*sSH[e*4+1] + vv[1]*sSH[e*4+2] + vv[2]*sSH[e*4+3]) * RSQRT3f;
    }
    // hE (both sets) -> sA bf16 hi/lo pairs: row e, words [kp0..31]=hi, [32..63]=lo
    {
      int e = t >> 2, kq = (t & 3) << 4;
#pragma unroll
      for (int s = 0; s < 2; s++){
        const float* W1s = sW1 + s*1024;
        const float* b1s = sW1 + 2048 + s*64;
        float v[16];
#pragma unroll
        for (int kk = 0; kk < 16; kk++){
          int k = kq + kk;
          float a = b1s[k];
#pragma unroll
          for (int b = 0; b < 16; b++) a += sEmb[e*16+b]*W1s[b*64+k];
          v[kk] = a/(1.f+expf(-a));
        }
        unsigned* arow = sA + s*4352 + e*ARS + (kq>>1);
#pragma unroll
        for (int p = 0; p < 8; p++){
          float x = v[2*p], y = v[2*p+1];
          __nv_bfloat16 hx = __float2bfloat16(x), hy = __float2bfloat16(y);
          arow[p]      = ((unsigned)__bfloat16_as_ushort(hy)<<16) | __bfloat16_as_ushort(hx);
          arow[32 + p] = packbf(x - __bfloat162float(hx), y - __bfloat162float(hy));
        }
      }
    }
    __syncthreads();

    // ---- main loop: 36 j-tiles of 128 (18 per set) ----
    for (int it = 0; it < 36; it++){
      int buf = it & 1;
      int s = (it >= 18) ? 1 : 0;
      int j0 = (it - s*18) << 7;

      if (it + 1 < 36){
        int s2 = ((it+1) >= 18) ? 1 : 0;
        int j02 = ((it+1) - s2*18) << 7;
        unsigned* db = sB + (buf^1)*BBUF;
        int colw = (t & 31) << 2;
        int rb = t >> 5;
#pragma unroll
        for (int q = 0; q < 8; q++){
          int r = rb + (q<<3);
          cp16(db + r*BRS + colw, d_W2p + (size_t)(s2*64 + r)*2304 + j02 + colw);
        }
        asm volatile("cp.async.commit_group;");
        asm volatile("cp.async.wait_group 1;");
      } else {
        asm volatile("cp.async.wait_group 0;");
      }
      __syncthreads();

      const unsigned* sBb = sB + buf*BBUF;
      const unsigned* sAs = sA + s*4352;

      // accumulators: 8 n-tiles x 4 f32, init with bias
      float acc[8][4];
      {
        const float* b2p = s ? b2v : b2k;
#pragma unroll
        for (int nt = 0; nt < 8; nt++){
          int jg = j0 + wn*64 + nt*8 + 2*c;
          float bx = b2p[jg], by = b2p[jg+1];
          acc[nt][0] = bx; acc[nt][1] = by; acc[nt][2] = bx; acc[nt][3] = by;
        }
      }
      // 3 terms: (Ahi,Bhi), (Alo,Bhi), (Ahi,Blo)
#pragma unroll
      for (int term = 0; term < 3; term++){
        int ab = (term == 1) ? 32 : 0;
        int bb = (term == 2) ? 32 : 0;
#pragma unroll
        for (int t8 = 0; t8 < 8; t8++){
          int kpb = t8 << 2;
          unsigned a0 = sAs[(e0+g)*ARS + ab + kpb + c];
          unsigned a1 = sAs[(e0+g+8)*ARS + ab + kpb + c];
          const unsigned* brow = sBb + (bb + kpb + c)*BRS + wn*64 + g;
#pragma unroll
          for (int nt = 0; nt < 8; nt++){
            unsigned b0 = brow[nt*8];
            mma_bf16(acc[nt][0], acc[nt][1], acc[nt][2], acc[nt][3], a0, a1, b0);
          }
        }
      }

      // stage w tile fp32 into sWT [e][132]
#pragma unroll
      for (int nt = 0; nt < 8; nt++){
        int jl = wn*64 + nt*8 + 2*c;
        *(float2*)(sWT + (e0+g)*WTP + jl)   = make_float2(acc[nt][0], acc[nt][1]);
        *(float2*)(sWT + (e0+g+8)*WTP + jl) = make_float2(acc[nt][2], acc[nt][3]);
      }
      __syncthreads();

      // epilogue: two 64-j sub-blocks
#pragma unroll
      for (int sb = 0; sb < 2; sb++){
        int gj = j0 + (sb<<6);
        int h = gj/576, off0 = gj - h*576;
        const float* wB = sWT + (sb<<6);
        if (off0 < 256){                     // ss -> out0 (coeff ss[u]*sh0)
          int u0 = off0 >> 3;
          for (int p = t; p < 512; p += 256){
            int e = p >> 3, ow = p & 7;
            const float* wr = wB + e*WTP + ow;
            float a = 0.f;
#pragma unroll
            for (int du = 0; du < 8; du++) a += sSS[e*32+u0+du]*wr[du*8];
            sO0[s*2048 + e*32 + h*8 + ow] += a*sSH[e*4];
          }
        } else if (off0 < 384){              // vv -> out0 (coeff cvv[u])
          int u0 = (off0-256) >> 3;
          for (int p = t; p < 512; p += 256){
            int e = p >> 3, ow = p & 7;
            const float* wr = wB + e*WTP + ow;
            float a = 0.f;
#pragma unroll
            for (int du = 0; du < 8; du++) a += sCVV[e*16+u0+du]*wr[du*8];
            sO0[s*2048 + e*32 + h*8 + ow] += a;
          }
        } else if (off0 < 512){              // sv -> s1 (coeff ss[u])
          int u0 = (off0-384) >> 2;
          {
            int e = t >> 2, w1 = t & 3;
            const float* wr = wB + e*WTP + w1;
            float a = 0.f;
#pragma unroll
            for (int du = 0; du < 16; du++) a += sSS[e*32+u0+du]*wr[du*4];
            sS1[s*1024 + e*16 + h*4 + w1] += a;
          }
        } else {                             // vs -> v1 (coeff vv[u,i]*sh0)
          for (int p = t; p < 768; p += 256){
            int e = p/12, r = p - e*12, w1 = r/3, i = r - w1*3;
            const float* wr = wB + e*WTP + w1;
            float a = 0.f;
#pragma unroll
            for (int du = 0; du < 16; du++) a += sVV[e*48+du*3+i]*wr[du*4];
            sV1[s*3072 + e*48 + h*12 + w1*3 + i] += a*sSH[e*4];
          }
        }
      }
      __syncthreads();
    }

    // write v-set outputs
    for (int p = t; p < 2048; p += 256){
      int e = p >> 5, cc = p & 31;
      int eg = eg0 + e;
      if (eg < E) d_v0e[(size_t)eg*32 + cc] = sO0[2048 + e*32 + cc]*RFANf;
    }
    for (int p = t; p < 3072; p += 256){
      int e = p/48, r = p - e*48;
      int h = r/12, q = r - h*12, w1 = q/3, i = q - w1*3;
      int eg = eg0 + e;
      if (eg < E)
        d_v1e[(size_t)eg*48 + r] =
          (sS1[1024 + e*16 + h*4 + w1]*sSH[e*4+1+i] + sV1[3072 + e*48 + r])*RFANf;
    }

    // logits (k-set)
    {
      int e = t >> 2, h = t & 3;
      int eg = eg0 + e;
      int dst = sIdx[64 + e];
      float k0r[8];
#pragma unroll
      for (int w = 0; w < 8; w++) k0r[w] = sO0[e*32 + h*8 + w]*RFANf;
      const float* q0 = d_q0g + dst*32 + h*8;
      float l0 = 0.f;
#pragma unroll
      for (int v = 0; v < 8; v++){
        float tv = 0.f;
#pragma unroll
        for (int u = 0; u < 8; u++) tv += q0[u]*sWD[u*8+v];
        l0 += tv*k0r[v];
      }
      float k1r[12];
#pragma unroll
      for (int w1 = 0; w1 < 4; w1++)
#pragma unroll
        for (int i = 0; i < 3; i++)
          k1r[w1*3+i] = (sS1[e*16+h*4+w1]*sSH[e*4+1+i] + sV1[e*48+h*12+w1*3+i])*RFANf;
      const float* q1 = d_q1g + dst*48 + h*12;
      float l1 = 0.f;
#pragma unroll
      for (int u = 0; u < 4; u++)
#pragma unroll
        for (int v = 0; v < 4; v++){
          float d3 = q1[u*3]*k1r[v*3] + q1[u*3+1]*k1r[v*3+1] + q1[u*3+2]*k1r[v*3+2];
          l1 += sWD[64 + u*4 + v]*d3;
        }
      float lg = (l0 + l1*RSQRT3f)*0.025f;
      lg = fminf(fmaxf(lg, -10.f), 10.f);
      if (eg < E){
        d_logits[eg*4 + h] = lg;
        atomicMaxF(d_segmax + dst*4 + h, lg);
      }
    }
  }
}

__global__ void k_ex(const int* __restrict__ ei, int E){
  int t = blockIdx.x*blockDim.x+threadIdx.x;
  if (t >= E*4) return;
  int e = t >> 2, h = t & 3;
  int dst = ei[E + e];
  float ex = expf(d_logits[t] - d_segmax[dst*4+h]);
  d_exb[t] = ex;
  atomicAdd(d_denom + dst*4 + h, ex);
}

__global__ void k_agg(const int* __restrict__ ei, int E){
  int t = blockIdx.x*blockDim.x+threadIdx.x;
  if (t >= E*80) return;
  int e = t/80, r = t - e*80;
  int dst = ei[E + e];
  if (r < 32){
    int h = r >> 3;
    float alpha = d_exb[e*4+h]/(d_denom[dst*4+h] + 1e-12f);
    atomicAdd(d_agg0 + dst*32 + r, alpha*d_v0e[(size_t)e*32 + r]);
  } else {
    int r2 = r - 32, h = r2/12;
    float alpha = d_exb[e*4+h]/(d_denom[dst*4+h] + 1e-12f);
    atomicAdd(d_agg1 + dst*48 + r2, alpha*d_v1e[(size_t)e*48 + r2]);
  }
}

__global__ void k_node(const float* __restrict__ nf,
    const float* __restrict__ Wo0, const float* __restrict__ Wo1,
    const float* __restrict__ Wf10, const float* __restrict__ Wf11,
    const float* __restrict__ Wf20, const float* __restrict__ Wf21,
    float* __restrict__ out, int N)
{
  __shared__ float sx0[32], sx1[48], sa0[64], sa1[48];
  int n = blockIdx.x, t = threadIdx.x;
  if (t < 32){
    float acc = 0.f;
#pragma unroll
    for (int u = 0; u < 32; u++) acc += d_agg0[n*32+u]*Wo0[u*32+t];
    sx0[t] = nf[(size_t)n*80 + t] + acc*RS32f;
  } else if (t < 80){
    int r = t-32, w = r/3, i = r - w*3;
    float acc = 0.f;
#pragma unroll
    for (int u = 0; u < 16; u++) acc += d_agg1[n*48+u*3+i]*Wo1[u*16+w];
    sx1[r] = nf[(size_t)n*80 + 32 + r] + acc*0.25f;
  }
  __syncthreads();
  if (t < 64){
    float acc = 0.f;
#pragma unroll
    for (int u = 0; u < 32; u++) acc += sx0[u]*Wf10[u*64+t];
    float a = acc*RS32f;
    sa0[t] = a/(1.f+expf(-a));
  } else if (t < 112){
    int r = t-64, w = r/3, i = r - w*3;
    float acc = 0.f;
#pragma unroll
    for (int u = 0; u < 16; u++) acc += sx1[u*3+i]*Wf11[u*16+w];
    sa1[r] = acc*0.25f;
  }
  __syncthreads();
  if (t < 16){
    float x = sa1[t*3], y = sa1[t*3+1], z = sa1[t*3+2];
    float nm = sqrtf(x*x+y*y+z*z);
    float g = (nm < 1e-8f) ? 0.f : (nm/(1.f+expf(-nm)))/nm;
    sa1[t*3] = x*g; sa1[t*3+1] = y*g; sa1[t*3+2] = z*g;
  }
  __syncthreads();
  if (t < 32){
    float acc = 0.f;
#pragma unroll
    for (int u = 0; u < 64; u++) acc += sa0[u]*Wf20[u*32+t];
    out[(size_t)n*80 + t] = sx0[t] + acc*0.125f;
  } else if (t < 80){
    int r = t-32, w = r/3, i = r - w*3;
    float acc = 0.f;
#pragma unroll
    for (int u = 0; u < 16; u++) acc += sa1[u*3+i]*Wf21[u*16+w];
    out[(size_t)n*80 + t] = sx1[r] + acc*0.25f;
  }
}

extern "C" void kernel_launch(void* const* d_in, const int* in_sizes, int n_in,
                              void* d_out, int out_size){
  const float* nf   = (const float*)d_in[0];
  const int*   ei   = (const int*)  d_in[1];
  const float* esh  = (const float*)d_in[2];
  const float* emb  = (const float*)d_in[3];
  const float* Wq0  = (const float*)d_in[4];
  const float* Wq1  = (const float*)d_in[5];
  const float* Wk1  = (const float*)d_in[6];
  const float* bk1  = (const float*)d_in[7];
  const float* Wk2  = (const float*)d_in[8];
  const float* bk2  = (const float*)d_in[9];
  const float* Wv1  = (const float*)d_in[10];
  const float* bv1  = (const float*)d_in[11];
  const float* Wv2  = (const float*)d_in[12];
  const float* bv2  = (const float*)d_in[13];
  const float* Wd0  = (const float*)d_in[14];
  const float* Wd1  = (const float*)d_in[15];
  const float* Wo0  = (const float*)d_in[16];
  const float* Wo1  = (const float*)d_in[17];
  const float* Wf10 = (const float*)d_in[18];
  const float* Wf11 = (const float*)d_in[19];
  const float* Wf20 = (const float*)d_in[20];
  const float* Wf21 = (const float*)d_in[21];
  float* out = (float*)d_out;

  int N = in_sizes[0]/80;
  int E = in_sizes[1]/2;

  static int smCount = 0;
  if (!smCount){
    cudaFuncSetAttribute(k_edge, cudaFuncAttributeMaxDynamicSharedMemorySize, SMEM_BYTES);
    cudaDeviceGetAttribute(&smCount, cudaDevAttrMultiProcessorCount, 0);
    if (smCount <= 0) smCount = 148;
  }
  int nT = (E + 63)/64;
  int grid = nT < smCount ? nT : smCount;

  k_prep<<<(2*32*2304+255)/256, 256>>>(Wk2, Wv2);
  k_init<<<(N*48+255)/256, 256>>>(N);
  k_q<<<(N*80+255)/256, 256>>>(nf, Wq0, Wq1, N);
  k_edge<<<grid, 256, SMEM_BYTES>>>(nf, ei, esh, emb,
      Wk1, bk1, bk2, Wv1, bv1, bv2, Wd0, Wd1, N, E);
  k_ex<<<(E*4+255)/256, 256>>>(ei, E);
  k_agg<<<(E*80+255)/256, 256>>>(ei, E);
  k_node<<<N, 128>>>(nf, Wo0, Wo1, Wf10, Wf11, Wf20, Wf21, out, N);
}

// round 7
// speedup vs baseline: 2.0770x; 1.4474x over previous
#include <cuda_runtime.h>
#include <cuda_bf16.h>
#include <math.h>
#include <stdint.h>

#define MAX_N 2048
#define MAX_E 32768
#define RFANf   0.14433756729740643f  // 1/sqrt(48)
#define RSQRT3f 0.57735026918962576f
#define RS32f   0.17677669529663687f  // 1/sqrt(32)

__device__ float d_q0g[MAX_N*32];
__device__ float d_q1g[MAX_N*48];
__device__ float d_v0e[(size_t)MAX_E*32];
__device__ float d_v1e[(size_t)MAX_E*48];
__device__ float d_logits[MAX_E*4];
__device__ float d_exb[MAX_E*4];
__device__ float d_segmax[MAX_N*4];
__device__ float d_denom[MAX_N*4];
__device__ float d_agg0[MAX_N*32];
__device__ float d_agg1[MAX_N*48];
// W2 bf16 hi/lo, k-pair interleaved: row = set*64 + (lo?32:0) + kp, 2304 words/row
__device__ unsigned int d_W2p[128*2304];

__device__ __forceinline__ void atomicMaxF(float* a, float v){
  if (v >= 0.f) atomicMax((int*)a, __float_as_int(v));
  else atomicMin((unsigned int*)a, __float_as_uint(v));
}
__device__ __forceinline__ unsigned packbf(float x, float y){
  unsigned short ux = __bfloat16_as_ushort(__float2bfloat16(x));
  unsigned short uy = __bfloat16_as_ushort(__float2bfloat16(y));
  return ((unsigned)uy << 16) | (unsigned)ux;
}

__global__ void k_prep(const float* __restrict__ W2k, const float* __restrict__ W2v){
  int t = blockIdx.x*blockDim.x + threadIdx.x;
  if (t >= 2*32*2304) return;
  int s  = t / (32*2304);
  int r  = t - s*32*2304;
  int kp = r / 2304;
  int j  = r - kp*2304;
  const float* W = s ? W2v : W2k;
  float a0 = W[(2*kp)*2304 + j];
  float a1 = W[(2*kp+1)*2304 + j];
  __nv_bfloat16 h0 = __float2bfloat16(a0);
  __nv_bfloat16 h1 = __float2bfloat16(a1);
  d_W2p[(size_t)(s*64 + kp)*2304 + j]      = ((unsigned)__bfloat16_as_ushort(h1)<<16) | __bfloat16_as_ushort(h0);
  d_W2p[(size_t)(s*64 + 32 + kp)*2304 + j] = packbf(a0 - __bfloat162float(h0), a1 - __bfloat162float(h1));
}

__global__ void k_init(int N){
  int t = blockIdx.x*blockDim.x+threadIdx.x;
  if (t < N*4){ d_segmax[t] = -10.0f; d_denom[t] = 0.0f; }
  if (t < N*32) d_agg0[t] = 0.0f;
  if (t < N*48) d_agg1[t] = 0.0f;
}

__global__ void k_q(const float* __restrict__ nf, const float* __restrict__ Wq0,
                    const float* __restrict__ Wq1, int N){
  int t = blockIdx.x*blockDim.x+threadIdx.x;
  if (t >= N*80) return;
  int n = t/80, r = t - n*80;
  if (r < 32){
    int h = r>>3, w = r&7;
    const float* s = nf + (size_t)n*80;
    float acc = 0.f;
#pragma unroll
    for (int u = 0; u < 32; u++) acc += s[u]*Wq0[h*256+u*8+w];
    d_q0g[n*32+r] = acc*RS32f;
  } else {
    int rr = r-32, h = rr/12, q = rr - h*12, w = q/3, i = q - w*3;
    const float* v = nf + (size_t)n*80 + 32;
    float acc = 0.f;
#pragma unroll
    for (int u = 0; u < 16; u++) acc += v[u*3+i]*Wq1[h*64+u*4+w];
    d_q1g[n*48+rr] = acc*0.25f;
  }
}

// ---- smem layout (32-bit words), 32 edges per CTA ----
#define OFF_A    0        // 2 sets * 32e * 68
#define ARS      68
#define OFF_B    4352     // 64 rows * 136 (single buffer)
#define BRS      136
#define OFF_WT   13056    // 32*136 = 4352 ; aliased in setup: sW1(2176) + sEmb(512)
#define WTP      136
#define OFF_O0   17408    // 2*32*32
#define OFF_S1   19456    // 2*32*16
#define OFF_V1   20480    // 2*32*48
#define OFF_SS   23552    // 32*32
#define OFF_VV   24576    // 32*48
#define OFF_CVV  26112    // 32*16
#define OFF_SH   26624    // 32*4
#define OFF_IDX  26752    // 64
#define SMEM_WORDS 26816
#define SMEM_BYTES (SMEM_WORDS*4)   // 107264

__device__ __forceinline__ void cp16(void* dst, const void* src){
  uint32_t a = (uint32_t)__cvta_generic_to_shared(dst);
  asm volatile("cp.async.cg.shared.global [%0], [%1], 16;" :: "r"(a), "l"(src));
}
__device__ __forceinline__ void mma16(float* c, unsigned a0, unsigned a1, unsigned a2, unsigned a3,
                                      unsigned b0, unsigned b1){
  asm volatile(
    "mma.sync.aligned.m16n8k16.row.col.f32.bf16.bf16.f32 "
    "{%0,%1,%2,%3},{%4,%5,%6,%7},{%8,%9},{%0,%1,%2,%3};"
    : "+f"(c[0]), "+f"(c[1]), "+f"(c[2]), "+f"(c[3])
    : "r"(a0), "r"(a1), "r"(a2), "r"(a3), "r"(b0), "r"(b1));
}

__global__ void __launch_bounds__(256,2) k_edge(
    const float* __restrict__ nf, const int* __restrict__ ei,
    const float* __restrict__ esh, const float* __restrict__ emb,
    const float* __restrict__ W1k, const float* __restrict__ b1k,
    const float* __restrict__ b2k,
    const float* __restrict__ W1v, const float* __restrict__ b1v,
    const float* __restrict__ b2v,
    const float* __restrict__ Wd0, const float* __restrict__ Wd1,
    int N, int E)
{
  extern __shared__ float sm[];
  unsigned* sA  = (unsigned*)(sm + OFF_A);
  unsigned* sB  = (unsigned*)(sm + OFF_B);
  float* sWT  = sm + OFF_WT;
  float* sW1  = sm + OFF_WT;          // alias (setup only)
  float* sEmb = sm + OFF_WT + 2176;   // alias (setup only)
  float* sO0  = sm + OFF_O0;
  float* sS1  = sm + OFF_S1;
  float* sV1  = sm + OFF_V1;
  float* sSS  = sm + OFF_SS;
  float* sVV  = sm + OFF_VV;
  float* sCVV = sm + OFF_CVV;
  float* sSH  = sm + OFF_SH;
  int*   sIdx = (int*)(sm + OFF_IDX);

  const int t    = threadIdx.x;
  const int lane = t & 31;
  const int wid  = t >> 5;
  const int wm   = wid >> 2, wn = wid & 3;   // wm 0..1 (m16 rows), wn 0..3 (n32)
  const int g    = lane >> 2, c = lane & 3;
  const int rowA = (wm << 4) + g;
  const int nT   = (E + 31) >> 5;

  for (int et = blockIdx.x; et < nT; et += gridDim.x){
    const int eg0 = et << 5;
    __syncthreads();

    // prefetch B tile 0 (set 0, j0=0)
    {
      int r = t >> 2, part = t & 3;
      const unsigned* gsrc = d_W2p + (size_t)r*2304;
#pragma unroll
      for (int q = 0; q < 8; q++){
        int jw = (part + q*4) << 2;
        cp16(sB + r*BRS + jw, gsrc + jw);
      }
      asm volatile("cp.async.commit_group;");
    }

    if (t < 64){
      int e = t & 31, which = t >> 5;
      int eg = eg0 + e;
      sIdx[t] = (eg < E) ? ei[(size_t)which*E + eg] : 0;
    }
    if (t < 128){
      int e = t >> 2, cc = t & 3;
      int eg = eg0 + e;
      bool val = eg < E;
      sSH[e*4+cc] = val ? esh[(size_t)eg*4+cc] : 0.f;
      float4 z = make_float4(0,0,0,0);
      float4 d = val ? *(const float4*)(emb + (size_t)eg*16 + cc*4) : z;
      *(float4*)(sEmb + e*16 + cc*4) = d;
    }
    // stage W1/b1 (into sWT alias region)
    for (int i = t; i < 1024; i += 256){ sW1[i] = W1k[i]; sW1[1024+i] = W1v[i]; }
    if (t < 64){ sW1[2048+t] = b1k[t]; sW1[2112+t] = b1v[t]; }
    // zero sO0/sS1/sV1 (contiguous 6144 words)
    for (int i = t; i < 1536; i += 256) *(float4*)(sO0 + i*4) = make_float4(0,0,0,0);
    __syncthreads();

    // gather src node features (20 float4 per edge)
#pragma unroll
    for (int ph = 0; ph < 2; ph++){
      int p = t + ph*256;
      int e = p >> 4, f4 = p & 15;
      const float4* row = (const float4*)(nf + (size_t)sIdx[e]*80);
      float4 d = row[f4];
      if (f4 < 8) *((float4*)(sSS + e*32) + f4) = d;
      else        *((float4*)(sVV + e*48) + (f4-8)) = d;
    }
    if (t < 128){
      int e = t >> 2, f4 = 16 + (t & 3);
      const float4* row = (const float4*)(nf + (size_t)sIdx[e]*80);
      *((float4*)(sVV + e*48) + (f4-8)) = row[f4];
    }
    __syncthreads();

    // cvv
#pragma unroll
    for (int ph = 0; ph < 2; ph++){
      int p = t + ph*256;
      int e = p >> 4, u = p & 15;
      const float* vv = sVV + e*48 + u*3;
      sCVV[p] = (vv[0]*sSH[e*4+1] + vv[1]*sSH[e*4+2] + vv[2]*sSH[e*4+3]) * RSQRT3f;
    }
    // hE (both sets) -> sA bf16 hi/lo pairs
    {
      int e = t >> 3, kq = (t & 7) << 3;
#pragma unroll
      for (int s = 0; s < 2; s++){
        const float* W1s = sW1 + s*1024;
        const float* b1s = sW1 + 2048 + s*64;
        float v[8];
#pragma unroll
        for (int kk = 0; kk < 8; kk++){
          int k = kq + kk;
          float a = b1s[k];
#pragma unroll
          for (int b = 0; b < 16; b++) a += sEmb[e*16+b]*W1s[b*64+k];
          v[kk] = a/(1.f+expf(-a));
        }
        unsigned* arow = sA + s*2176 + e*ARS + (kq>>1);
#pragma unroll
        for (int p = 0; p < 4; p++){
          float x = v[2*p], y = v[2*p+1];
          __nv_bfloat16 hx = __float2bfloat16(x), hy = __float2bfloat16(y);
          arow[p]      = ((unsigned)__bfloat16_as_ushort(hy)<<16) | __bfloat16_as_ushort(hx);
          arow[32 + p] = packbf(x - __bfloat162float(hx), y - __bfloat162float(hy));
        }
      }
    }
    asm volatile("cp.async.wait_group 0;");
    __syncthreads();

    // ---- main loop: 36 j-tiles of 128 (18 per set), single-buffered B ----
    for (int it = 0; it < 36; it++){
      int s = (it >= 18) ? 1 : 0;
      int j0 = (it - s*18) << 7;

      // MMA: m16 x n32 per warp, bias init
      float acc[4][4];
      {
        const float* b2p = s ? b2v : b2k;
#pragma unroll
        for (int nt = 0; nt < 4; nt++){
          float2 bb = *(const float2*)(b2p + j0 + (wn<<5) + (nt<<3) + 2*c);
          acc[nt][0] = bb.x; acc[nt][1] = bb.y; acc[nt][2] = bb.x; acc[nt][3] = bb.y;
        }
      }
      const unsigned* sAs = sA + s*2176;
      const unsigned* aP  = sAs + rowA*ARS;
      const unsigned* aP8 = sAs + (rowA+8)*ARS;
#pragma unroll
      for (int ks = 0; ks < 4; ks++){
        int kb = ks*8 + c;
        unsigned ah0 = aP[kb],    ah2 = aP[kb+4];
        unsigned ah1 = aP8[kb],   ah3 = aP8[kb+4];
        unsigned al0 = aP[32+kb], al2 = aP[32+kb+4];
        unsigned al1 = aP8[32+kb],al3 = aP8[32+kb+4];
#pragma unroll
        for (int nt = 0; nt < 4; nt++){
          const unsigned* bP = sB + kb*BRS + (wn<<5) + (nt<<3) + g;
          unsigned bh0 = bP[0],        bh1 = bP[4*BRS];
          unsigned bl0 = bP[32*BRS],   bl1 = bP[36*BRS];
          mma16(acc[nt], ah0,ah1,ah2,ah3, bh0,bh1);
          mma16(acc[nt], al0,al1,al2,al3, bh0,bh1);
          mma16(acc[nt], ah0,ah1,ah2,ah3, bl0,bl1);
        }
      }
      // stage w tile
#pragma unroll
      for (int nt = 0; nt < 4; nt++){
        int jl = (wn<<5) + (nt<<3) + 2*c;
        *(float2*)(sWT + rowA*WTP + jl)     = make_float2(acc[nt][0], acc[nt][1]);
        *(float2*)(sWT + (rowA+8)*WTP + jl) = make_float2(acc[nt][2], acc[nt][3]);
      }
      __syncthreads();   // sWT staged; sB fully consumed

      // prefetch next B tile (overlaps epilogue)
      if (it + 1 < 36){
        int s2 = ((it+1) >= 18) ? 1 : 0;
        int j02 = ((it+1) - s2*18) << 7;
        int r = t >> 2, part = t & 3;
        const unsigned* gsrc = d_W2p + (size_t)(s2*64 + r)*2304 + j02;
#pragma unroll
        for (int q = 0; q < 8; q++){
          int jw = (part + q*4) << 2;
          cp16(sB + r*BRS + jw, gsrc + jw);
        }
        asm volatile("cp.async.commit_group;");
      }

      // epilogue: two 64-j sub-blocks
#pragma unroll
      for (int sb = 0; sb < 2; sb++){
        int gj = j0 + (sb<<6);
        int h = gj/576, off0 = gj - h*576;
        const float* wB = sWT + (sb<<6);
        if (off0 < 256){                     // ss -> out0 (coeff ss[u]*sh0)
          int u0 = off0 >> 3;
          int e = t >> 3, ow = t & 7;
          const float* wr = wB + e*WTP + ow;
          float a = 0.f;
#pragma unroll
          for (int du = 0; du < 8; du++) a += sSS[e*32+u0+du]*wr[du*8];
          sO0[s*1024 + e*32 + h*8 + ow] += a*sSH[e*4];
        } else if (off0 < 384){              // vv -> out0 (coeff cvv[u])
          int u0 = (off0-256) >> 3;
          int e = t >> 3, ow = t & 7;
          const float* wr = wB + e*WTP + ow;
          float a = 0.f;
#pragma unroll
          for (int du = 0; du < 8; du++) a += sCVV[e*16+u0+du]*wr[du*8];
          sO0[s*1024 + e*32 + h*8 + ow] += a;
        } else if (off0 < 512){              // sv -> s1 (coeff ss[u])
          if (t < 128){
            int u0 = (off0-384) >> 2;
            int e = t >> 2, w1 = t & 3;
            const float* wr = wB + e*WTP + w1;
            float a = 0.f;
#pragma unroll
            for (int du = 0; du < 16; du++) a += sSS[e*32+u0+du]*wr[du*4];
            sS1[s*512 + e*16 + h*4 + w1] += a;
          }
        } else {                             // vs -> v1 (coeff vv[u,i]*sh0)
          for (int p = t; p < 384; p += 256){
            int e = p/12, r = p - e*12, w1 = r/3, i = r - w1*3;
            const float* wr = wB + e*WTP + w1;
            float a = 0.f;
#pragma unroll
            for (int du = 0; du < 16; du++) a += sVV[e*48+du*3+i]*wr[du*4];
            sV1[s*1536 + e*48 + h*12 + w1*3 + i] += a*sSH[e*4];
          }
        }
      }
      asm volatile("cp.async.wait_group 0;");
      __syncthreads();
    }

    // write v-set outputs
#pragma unroll
    for (int ph = 0; ph < 4; ph++){
      int p = t + ph*256;
      int e = p >> 5, cc = p & 31;
      int eg = eg0 + e;
      if (eg < E) d_v0e[(size_t)eg*32 + cc] = sO0[1024 + e*32 + cc]*RFANf;
    }
    for (int p = t; p < 1536; p += 256){
      int e = p/48, r = p - e*48;
      int h = r/12, q = r - h*12, w1 = q/3, i = q - w1*3;
      int eg = eg0 + e;
      if (eg < E)
        d_v1e[(size_t)eg*48 + r] =
          (sS1[512 + e*16 + h*4 + w1]*sSH[e*4+1+i] + sV1[1536 + e*48 + r])*RFANf;
    }

    // logits (k-set)
    if (t < 128){
      int e = t >> 2, h = t & 3;
      int eg = eg0 + e;
      int dst = sIdx[32 + e];
      float k0r[8];
#pragma unroll
      for (int w = 0; w < 8; w++) k0r[w] = sO0[e*32 + h*8 + w]*RFANf;
      const float* q0 = d_q0g + dst*32 + h*8;
      float l0 = 0.f;
#pragma unroll
      for (int v = 0; v < 8; v++){
        float tv = 0.f;
#pragma unroll
        for (int u = 0; u < 8; u++) tv += q0[u]*Wd0[u*8+v];
        l0 += tv*k0r[v];
      }
      float k1r[12];
#pragma unroll
      for (int w1 = 0; w1 < 4; w1++)
#pragma unroll
        for (int i = 0; i < 3; i++)
          k1r[w1*3+i] = (sS1[e*16+h*4+w1]*sSH[e*4+1+i] + sV1[e*48+h*12+w1*3+i])*RFANf;
      const float* q1 = d_q1g + dst*48 + h*12;
      float l1 = 0.f;
#pragma unroll
      for (int u = 0; u < 4; u++)
#pragma unroll
        for (int v = 0; v < 4; v++){
          float d3 = q1[u*3]*k1r[v*3] + q1[u*3+1]*k1r[v*3+1] + q1[u*3+2]*k1r[v*3+2];
          l1 += Wd1[u*4 + v]*d3;
        }
      float lg = (l0 + l1*RSQRT3f)*0.025f;
      lg = fminf(fmaxf(lg, -10.f), 10.f);
      if (eg < E){
        d_logits[eg*4 + h] = lg;
        atomicMaxF(d_segmax + dst*4 + h, lg);
      }
    }
  }
}

__global__ void k_ex(const int* __restrict__ ei, int E){
  int t = blockIdx.x*blockDim.x+threadIdx.x;
  if (t >= E*4) return;
  int e = t >> 2, h = t & 3;
  int dst = ei[E + e];
  float ex = expf(d_logits[t] - d_segmax[dst*4+h]);
  d_exb[t] = ex;
  atomicAdd(d_denom + dst*4 + h, ex);
}

__global__ void k_agg(const int* __restrict__ ei, int E){
  int t = blockIdx.x*blockDim.x+threadIdx.x;
  if (t >= E*80) return;
  int e = t/80, r = t - e*80;
  int dst = ei[E + e];
  if (r < 32){
    int h = r >> 3;
    float alpha = d_exb[e*4+h]/(d_denom[dst*4+h] + 1e-12f);
    atomicAdd(d_agg0 + dst*32 + r, alpha*d_v0e[(size_t)e*32 + r]);
  } else {
    int r2 = r - 32, h = r2/12;
    float alpha = d_exb[e*4+h]/(d_denom[dst*4+h] + 1e-12f);
    atomicAdd(d_agg1 + dst*48 + r2, alpha*d_v1e[(size_t)e*48 + r2]);
  }
}

__global__ void k_node(const float* __restrict__ nf,
    const float* __restrict__ Wo0, const float* __restrict__ Wo1,
    const float* __restrict__ Wf10, const float* __restrict__ Wf11,
    const float* __restrict__ Wf20, const float* __restrict__ Wf21,
    float* __restrict__ out, int N)
{
  __shared__ float sx0[32], sx1[48], sa0[64], sa1[48];
  int n = blockIdx.x, t = threadIdx.x;
  if (t < 32){
    float acc = 0.f;
#pragma unroll
    for (int u = 0; u < 32; u++) acc += d_agg0[n*32+u]*Wo0[u*32+t];
    sx0[t] = nf[(size_t)n*80 + t] + acc*RS32f;
  } else if (t < 80){
    int r = t-32, w = r/3, i = r - w*3;
    float acc = 0.f;
#pragma unroll
    for (int u = 0; u < 16; u++) acc += d_agg1[n*48+u*3+i]*Wo1[u*16+w];
    sx1[r] = nf[(size_t)n*80 + 32 + r] + acc*0.25f;
  }
  __syncthreads();
  if (t < 64){
    float acc = 0.f;
#pragma unroll
    for (int u = 0; u < 32; u++) acc += sx0[u]*Wf10[u*64+t];
    float a = acc*RS32f;
    sa0[t] = a/(1.f+expf(-a));
  } else if (t < 112){
    int r = t-64, w = r/3, i = r - w*3;
    float acc = 0.f;
#pragma unroll
    for (int u = 0; u < 16; u++) acc += sx1[u*3+i]*Wf11[u*16+w];
    sa1[r] = acc*0.25f;
  }
  __syncthreads();
  if (t < 16){
    float x = sa1[t*3], y = sa1[t*3+1], z = sa1[t*3+2];
    float nm = sqrtf(x*x+y*y+z*z);
    float g = (nm < 1e-8f) ? 0.f : (nm/(1.f+expf(-nm)))/nm;
    sa1[t*3] = x*g; sa1[t*3+1] = y*g; sa1[t*3+2] = z*g;
  }
  __syncthreads();
  if (t < 32){
    float acc = 0.f;
#pragma unroll
    for (int u = 0; u < 64; u++) acc += sa0[u]*Wf20[u*32+t];
    out[(size_t)n*80 + t] = sx0[t] + acc*0.125f;
  } else if (t < 80){
    int r = t-32, w = r/3, i = r - w*3;
    float acc = 0.f;
#pragma unroll
    for (int u = 0; u < 16; u++) acc += sa1[u*3+i]*Wf21[u*16+w];
    out[(size_t)n*80 + t] = sx1[r] + acc*0.25f;
  }
}

extern "C" void kernel_launch(void* const* d_in, const int* in_sizes, int n_in,
                              void* d_out, int out_size){
  const float* nf   = (const float*)d_in[0];
  const int*   ei   = (const int*)  d_in[1];
  const float* esh  = (const float*)d_in[2];
  const float* emb  = (const float*)d_in[3];
  const float* Wq0  = (const float*)d_in[4];
  const float* Wq1  = (const float*)d_in[5];
  const float* Wk1  = (const float*)d_in[6];
  const float* bk1  = (const float*)d_in[7];
  const float* Wk2  = (const float*)d_in[8];
  const float* bk2  = (const float*)d_in[9];
  const float* Wv1  = (const float*)d_in[10];
  const float* bv1  = (const float*)d_in[11];
  const float* Wv2  = (const float*)d_in[12];
  const float* bv2  = (const float*)d_in[13];
  const float* Wd0  = (const float*)d_in[14];
  const float* Wd1  = (const float*)d_in[15];
  const float* Wo0  = (const float*)d_in[16];
  const float* Wo1  = (const float*)d_in[17];
  const float* Wf10 = (const float*)d_in[18];
  const float* Wf11 = (const float*)d_in[19];
  const float* Wf20 = (const float*)d_in[20];
  const float* Wf21 = (const float*)d_in[21];
  float* out = (float*)d_out;

  int N = in_sizes[0]/80;
  int E = in_sizes[1]/2;

  static int smCount = 0;
  if (!smCount){
    cudaFuncSetAttribute(k_edge, cudaFuncAttributeMaxDynamicSharedMemorySize, SMEM_BYTES);
    cudaDeviceGetAttribute(&smCount, cudaDevAttrMultiProcessorCount, 0);
    if (smCount <= 0) smCount = 148;
  }
  int nT = (E + 31)/32;
  int grid = nT < 2*smCount ? nT : 2*smCount;

  k_prep<<<(2*32*2304+255)/256, 256>>>(Wk2, Wv2);
  k_init<<<(N*48+255)/256, 256>>>(N);
  k_q<<<(N*80+255)/256, 256>>>(nf, Wq0, Wq1, N);
  k_edge<<<grid, 256, SMEM_BYTES>>>(nf, ei, esh, emb,
      Wk1, bk1, bk2, Wv1, bv1, bv2, Wd0, Wd1, N, E);
  k_ex<<<(E*4+255)/256, 256>>>(ei, E);
  k_agg<<<(E*80+255)/256, 256>>>(ei, E);
  k_node<<<N, 128>>>(nf, Wo0, Wo1, Wf10, Wf11, Wf20, Wf21, out, N);
}

// round 8
// speedup vs baseline: 2.3340x; 1.1238x over previous
#include <cuda_runtime.h>
#include <cuda_bf16.h>
#include <math.h>
#include <stdint.h>

#define MAX_N 2048
#define MAX_E 32768
#define RFANf   0.14433756729740643f  // 1/sqrt(48)
#define RSQRT3f 0.57735026918962576f
#define RS32f   0.17677669529663687f  // 1/sqrt(32)

__device__ float d_q0g[MAX_N*32];
__device__ float d_q1g[MAX_N*48];
__device__ float d_v0e[(size_t)MAX_E*32];
__device__ float d_v1e[(size_t)MAX_E*48];
__device__ float d_logits[MAX_E*4];
__device__ float d_exb[MAX_E*4];
__device__ float d_segmax[MAX_N*4];
__device__ float d_denom[MAX_N*4];
__device__ float d_agg0[MAX_N*32];
__device__ float d_agg1[MAX_N*48];
// W2 bf16 hi/lo, k-pair interleaved: row = set*64 + (lo?32:0) + kp, 2304 words/row
__device__ unsigned int d_W2p[128*2304];

__device__ __forceinline__ void atomicMaxF(float* a, float v){
  if (v >= 0.f) atomicMax((int*)a, __float_as_int(v));
  else atomicMin((unsigned int*)a, __float_as_uint(v));
}
__device__ __forceinline__ unsigned packbf(float x, float y){
  unsigned short ux = __bfloat16_as_ushort(__float2bfloat16(x));
  unsigned short uy = __bfloat16_as_ushort(__float2bfloat16(y));
  return ((unsigned)uy << 16) | (unsigned)ux;
}

__global__ void k_prep(const float* __restrict__ W2k, const float* __restrict__ W2v){
  int t = blockIdx.x*blockDim.x + threadIdx.x;
  if (t >= 2*32*2304) return;
  int s  = t / (32*2304);
  int r  = t - s*32*2304;
  int kp = r / 2304;
  int j  = r - kp*2304;
  const float* W = s ? W2v : W2k;
  float a0 = W[(2*kp)*2304 + j];
  float a1 = W[(2*kp+1)*2304 + j];
  __nv_bfloat16 h0 = __float2bfloat16(a0);
  __nv_bfloat16 h1 = __float2bfloat16(a1);
  d_W2p[(size_t)(s*64 + kp)*2304 + j]      = ((unsigned)__bfloat16_as_ushort(h1)<<16) | __bfloat16_as_ushort(h0);
  d_W2p[(size_t)(s*64 + 32 + kp)*2304 + j] = packbf(a0 - __bfloat162float(h0), a1 - __bfloat162float(h1));
}

__global__ void k_init(int N){
  int t = blockIdx.x*blockDim.x+threadIdx.x;
  if (t < N*4){ d_segmax[t] = -10.0f; d_denom[t] = 0.0f; }
  if (t < N*32) d_agg0[t] = 0.0f;
  if (t < N*48) d_agg1[t] = 0.0f;
}

__global__ void k_q(const float* __restrict__ nf, const float* __restrict__ Wq0,
                    const float* __restrict__ Wq1, int N){
  int t = blockIdx.x*blockDim.x+threadIdx.x;
  if (t >= N*80) return;
  int n = t/80, r = t - n*80;
  if (r < 32){
    int h = r>>3, w = r&7;
    const float* s = nf + (size_t)n*80;
    float acc = 0.f;
#pragma unroll
    for (int u = 0; u < 32; u++) acc += s[u]*Wq0[h*256+u*8+w];
    d_q0g[n*32+r] = acc*RS32f;
  } else {
    int rr = r-32, h = rr/12, q = rr - h*12, w = q/3, i = q - w*3;
    const float* v = nf + (size_t)n*80 + 32;
    float acc = 0.f;
#pragma unroll
    for (int u = 0; u < 16; u++) acc += v[u*3+i]*Wq1[h*64+u*4+w];
    d_q1g[n*48+rr] = acc*0.25f;
  }
}

// ---- smem layout (32-bit words), 32 edges/CTA, current-set-only ----
#define OFF_A    0        // 32e * 68 (hi kp0..31, lo 32..63, pad 4)
#define ARS      68
#define OFF_B    2176     // 64 rows * 72 (64-j tile)
#define BRS      72
#define OFF_WT   6784     // 32*72 ; aliased in setup: W1s(1024)+b1s(64)
#define WTP      72
#define OFF_O0   9088     // 32*32
#define OFF_S1   10112    // 32*16
#define OFF_V1   10624    // 32*48
#define OFF_SS   12160    // 32*32
#define OFF_VV   13184    // 32*48
#define OFF_CVV  14720    // 32*16
#define OFF_SH   15232    // 32*4
#define OFF_EMB  15360    // 32*16
#define OFF_IDX  15872    // 64
#define SMEM_WORDS 15936
#define SMEM_BYTES (SMEM_WORDS*4)   // 63744

__device__ __forceinline__ void cp16(void* dst, const void* src){
  uint32_t a = (uint32_t)__cvta_generic_to_shared(dst);
  asm volatile("cp.async.cg.shared.global [%0], [%1], 16;" :: "r"(a), "l"(src));
}
__device__ __forceinline__ void mma16(float* c, unsigned a0, unsigned a1, unsigned a2, unsigned a3,
                                      unsigned b0, unsigned b1){
  asm volatile(
    "mma.sync.aligned.m16n8k16.row.col.f32.bf16.bf16.f32 "
    "{%0,%1,%2,%3},{%4,%5,%6,%7},{%8,%9},{%0,%1,%2,%3};"
    : "+f"(c[0]), "+f"(c[1]), "+f"(c[2]), "+f"(c[3])
    : "r"(a0), "r"(a1), "r"(a2), "r"(a3), "r"(b0), "r"(b1));
}

__global__ void __launch_bounds__(256,3) k_edge(
    const float* __restrict__ nf, const int* __restrict__ ei,
    const float* __restrict__ esh, const float* __restrict__ emb,
    const float* __restrict__ W1k, const float* __restrict__ b1k,
    const float* __restrict__ b2k,
    const float* __restrict__ W1v, const float* __restrict__ b1v,
    const float* __restrict__ b2v,
    const float* __restrict__ Wd0, const float* __restrict__ Wd1,
    int N, int E)
{
  extern __shared__ float sm[];
  unsigned* sA  = (unsigned*)(sm + OFF_A);
  unsigned* sB  = (unsigned*)(sm + OFF_B);
  float* sWT  = sm + OFF_WT;
  float* sW1  = sm + OFF_WT;   // alias (set-setup only)
  float* sO0  = sm + OFF_O0;
  float* sS1  = sm + OFF_S1;
  float* sV1  = sm + OFF_V1;
  float* sSS  = sm + OFF_SS;
  float* sVV  = sm + OFF_VV;
  float* sCVV = sm + OFF_CVV;
  float* sSH  = sm + OFF_SH;
  float* sEmb = sm + OFF_EMB;
  int*   sIdx = (int*)(sm + OFF_IDX);

  const int t    = threadIdx.x;
  const int lane = t & 31;
  const int wid  = t >> 5;
  const int wm   = wid >> 2, wn = wid & 3;   // warp: m16 (wm) x n16 (wn)
  const int g    = lane >> 2, c = lane & 3;
  const int rowA = (wm << 4) + g;
  const int nT   = (E + 31) >> 5;

  for (int et = blockIdx.x; et < nT; et += gridDim.x){
    const int eg0 = et << 5;
    __syncthreads();

    // prefetch B chunk 0 (set 0, j0=0): 64 rows x 64 words
    {
      int r = t >> 2, part = t & 3;
      const unsigned* gsrc = d_W2p + (size_t)r*2304;
#pragma unroll
      for (int q = 0; q < 4; q++){
        int jw = (part << 2) + (q << 4);
        cp16(sB + r*BRS + jw, gsrc + jw);
      }
      asm volatile("cp.async.commit_group;");
    }

    if (t < 64){
      int e = t & 31, which = t >> 5;
      int eg = eg0 + e;
      sIdx[t] = (eg < E) ? ei[(size_t)which*E + eg] : 0;
    }
    if (t < 128){
      int e = t >> 2, cc = t & 3;
      int eg = eg0 + e;
      bool val = eg < E;
      sSH[e*4+cc] = val ? esh[(size_t)eg*4+cc] : 0.f;
      float4 z = make_float4(0,0,0,0);
      float4 d = val ? *(const float4*)(emb + (size_t)eg*16 + cc*4) : z;
      *(float4*)(sEmb + e*16 + cc*4) = d;
    }
    __syncthreads();

    // gather src node features (20 float4 per edge)
#pragma unroll
    for (int ph = 0; ph < 2; ph++){
      int p = t + ph*256;
      int e = p >> 4, f4 = p & 15;
      const float4* row = (const float4*)(nf + (size_t)sIdx[e]*80);
      float4 d = row[f4];
      if (f4 < 8) *((float4*)(sSS + e*32) + f4) = d;
      else        *((float4*)(sVV + e*48) + (f4-8)) = d;
    }
    if (t < 128){
      int e = t >> 2, f4 = 16 + (t & 3);
      const float4* row = (const float4*)(nf + (size_t)sIdx[e]*80);
      *((float4*)(sVV + e*48) + (f4-8)) = row[f4];
    }
    __syncthreads();

    // cvv
#pragma unroll
    for (int ph = 0; ph < 2; ph++){
      int p = t + ph*256;
      int e = p >> 4, u = p & 15;
      const float* vv = sVV + e*48 + u*3;
      sCVV[p] = (vv[0]*sSH[e*4+1] + vv[1]*sSH[e*4+2] + vv[2]*sSH[e*4+3]) * RSQRT3f;
    }

    // ---- two sets, sequential; accumulators + A reused ----
#pragma unroll 1
    for (int s = 0; s < 2; s++){
      if (s == 1){
        // logits from k-set accumulators (before they are re-zeroed)
        __syncthreads();
        if (t < 128){
          int e = t >> 2, h = t & 3;
          int eg = eg0 + e;
          int dst = sIdx[32 + e];
          float k0r[8];
#pragma unroll
          for (int w = 0; w < 8; w++) k0r[w] = sO0[e*32 + h*8 + w]*RFANf;
          const float* q0 = d_q0g + dst*32 + h*8;
          float l0 = 0.f;
#pragma unroll
          for (int v = 0; v < 8; v++){
            float tv = 0.f;
#pragma unroll
            for (int u = 0; u < 8; u++) tv += q0[u]*Wd0[u*8+v];
            l0 += tv*k0r[v];
          }
          float k1r[12];
#pragma unroll
          for (int w1 = 0; w1 < 4; w1++)
#pragma unroll
            for (int i = 0; i < 3; i++)
              k1r[w1*3+i] = (sS1[e*16+h*4+w1]*sSH[e*4+1+i] + sV1[e*48+h*12+w1*3+i])*RFANf;
          const float* q1 = d_q1g + dst*48 + h*12;
          float l1 = 0.f;
#pragma unroll
          for (int u = 0; u < 4; u++)
#pragma unroll
            for (int v = 0; v < 4; v++){
              float d3 = q1[u*3]*k1r[v*3] + q1[u*3+1]*k1r[v*3+1] + q1[u*3+2]*k1r[v*3+2];
              l1 += Wd1[u*4 + v]*d3;
            }
          float lg = (l0 + l1*RSQRT3f)*0.025f;
          lg = fminf(fmaxf(lg, -10.f), 10.f);
          if (eg < E){
            d_logits[eg*4 + h] = lg;
            atomicMaxF(d_segmax + dst*4 + h, lg);
          }
        }
        __syncthreads();
      }

      // stage W1/b1 for this set into sWT alias; zero accumulators
      {
        const float* W1s = s ? W1v : W1k;
        const float* b1s = s ? b1v : b1k;
        for (int i = t; i < 1024; i += 256) sW1[i] = W1s[i];
        if (t < 64) sW1[1024+t] = b1s[t];
        for (int i = t; i < 768; i += 256) *(float4*)(sO0 + i*4) = make_float4(0,0,0,0);
      }
      __syncthreads();

      // hE for this set -> sA (bf16 hi/lo pairs)
      {
        int e = t >> 3, kq = (t & 7) << 3;
        float v[8];
#pragma unroll
        for (int kk = 0; kk < 8; kk++){
          int k = kq + kk;
          float a = sW1[1024 + k];
#pragma unroll
          for (int b = 0; b < 16; b++) a += sEmb[e*16+b]*sW1[b*64+k];
          v[kk] = a/(1.f+expf(-a));
        }
        unsigned* arow = sA + e*ARS + (kq>>1);
#pragma unroll
        for (int p = 0; p < 4; p++){
          float x = v[2*p], y = v[2*p+1];
          __nv_bfloat16 hx = __float2bfloat16(x), hy = __float2bfloat16(y);
          arow[p]      = ((unsigned)__bfloat16_as_ushort(hy)<<16) | __bfloat16_as_ushort(hx);
          arow[32 + p] = packbf(x - __bfloat162float(hx), y - __bfloat162float(hy));
        }
      }
      __syncthreads();

      // hoist A fragments into registers for the whole set
      unsigned ah[4][4], al[4][4];
      {
        const unsigned* aP  = sA + rowA*ARS;
        const unsigned* aP8 = sA + (rowA+8)*ARS;
#pragma unroll
        for (int ks = 0; ks < 4; ks++){
          int kb = ks*8 + c;
          ah[ks][0] = aP[kb];    ah[ks][1] = aP8[kb];
          ah[ks][2] = aP[kb+4];  ah[ks][3] = aP8[kb+4];
          al[ks][0] = aP[32+kb]; al[ks][1] = aP8[32+kb];
          al[ks][2] = aP[32+kb+4]; al[ks][3] = aP8[32+kb+4];
        }
      }

      // ---- 36 tiles of 64 j ----
      for (int it = 0; it < 36; it++){
        int j0 = it << 6;
        int ct = s*36 + it;

        // MMA m16 x n16 per warp, bias init
        float acc[2][4];
        {
          const float* b2p = s ? b2v : b2k;
#pragma unroll
          for (int nt = 0; nt < 2; nt++){
            float2 bb = *(const float2*)(b2p + j0 + (wn<<4) + (nt<<3) + 2*c);
            acc[nt][0] = bb.x; acc[nt][1] = bb.y; acc[nt][2] = bb.x; acc[nt][3] = bb.y;
          }
        }
#pragma unroll
        for (int ks = 0; ks < 4; ks++){
          int kb = ks*8 + c;
#pragma unroll
          for (int nt = 0; nt < 2; nt++){
            const unsigned* bP = sB + kb*BRS + (wn<<4) + (nt<<3) + g;
            unsigned bh0 = bP[0],      bh1 = bP[4*BRS];
            unsigned bl0 = bP[32*BRS], bl1 = bP[36*BRS];
            mma16(acc[nt], ah[ks][0],ah[ks][1],ah[ks][2],ah[ks][3], bh0,bh1);
            mma16(acc[nt], al[ks][0],al[ks][1],al[ks][2],al[ks][3], bh0,bh1);
            mma16(acc[nt], ah[ks][0],ah[ks][1],ah[ks][2],ah[ks][3], bl0,bl1);
          }
        }
        // stage w tile
#pragma unroll
        for (int nt = 0; nt < 2; nt++){
          int jl = (wn<<4) + (nt<<3) + 2*c;
          *(float2*)(sWT + rowA*WTP + jl)     = make_float2(acc[nt][0], acc[nt][1]);
          *(float2*)(sWT + (rowA+8)*WTP + jl) = make_float2(acc[nt][2], acc[nt][3]);
        }
        __syncthreads();   // sWT staged; sB consumed

        // prefetch next B chunk (overlaps epilogue)
        if (ct + 1 < 72){
          int s2 = (ct+1 >= 36) ? 1 : 0;
          int j02 = ((ct+1) - s2*36) << 6;
          int r = t >> 2, part = t & 3;
          const unsigned* gsrc = d_W2p + (size_t)(s2*64 + r)*2304 + j02;
#pragma unroll
          for (int q = 0; q < 4; q++){
            int jw = (part << 2) + (q << 4);
            cp16(sB + r*BRS + jw, gsrc + jw);
          }
          asm volatile("cp.async.commit_group;");
        }

        // epilogue: contract this 64-j block
        {
          int h = j0/576, off0 = j0 - h*576;
          if (off0 < 256){                     // ss -> out0 (coeff ss[u]*sh0)
            int u0 = off0 >> 3;
            int e = t >> 3, ow = t & 7;
            const float* wr = sWT + e*WTP + ow;
            float a = 0.f;
#pragma unroll
            for (int du = 0; du < 8; du++) a += sSS[e*32+u0+du]*wr[du*8];
            sO0[e*32 + h*8 + ow] += a*sSH[e*4];
          } else if (off0 < 384){              // vv -> out0 (coeff cvv[u])
            int u0 = (off0-256) >> 3;
            int e = t >> 3, ow = t & 7;
            const float* wr = sWT + e*WTP + ow;
            float a = 0.f;
#pragma unroll
            for (int du = 0; du < 8; du++) a += sCVV[e*16+u0+du]*wr[du*8];
            sO0[e*32 + h*8 + ow] += a;
          } else if (off0 < 512){              // sv -> s1 (coeff ss[u])
            if (t < 128){
              int u0 = (off0-384) >> 2;
              int e = t >> 2, w1 = t & 3;
              const float* wr = sWT + e*WTP + w1;
              float a = 0.f;
#pragma unroll
              for (int du = 0; du < 16; du++) a += sSS[e*32+u0+du]*wr[du*4];
              sS1[e*16 + h*4 + w1] += a;
            }
          } else {                             // vs -> v1 (coeff vv[u,i]*sh0)
            for (int p = t; p < 384; p += 256){
              int e = p/12, r = p - e*12, w1 = r/3, i = r - w1*3;
              const float* wr = sWT + e*WTP + w1;
              float a = 0.f;
#pragma unroll
              for (int du = 0; du < 16; du++) a += sVV[e*48+du*3+i]*wr[du*4];
              sV1[e*48 + h*12 + w1*3 + i] += a*sSH[e*4];
            }
          }
        }
        asm volatile("cp.async.wait_group 0;");
        __syncthreads();
      }
    }

    // write v-set outputs (accumulators hold set 1 now)
#pragma unroll
    for (int ph = 0; ph < 4; ph++){
      int p = t + ph*256;
      int e = p >> 5, cc = p & 31;
      int eg = eg0 + e;
      if (eg < E) d_v0e[(size_t)eg*32 + cc] = sO0[e*32 + cc]*RFANf;
    }
    for (int p = t; p < 1536; p += 256){
      int e = p/48, r = p - e*48;
      int h = r/12, q = r - h*12, w1 = q/3, i = q - w1*3;
      int eg = eg0 + e;
      if (eg < E)
        d_v1e[(size_t)eg*48 + r] =
          (sS1[e*16 + h*4 + w1]*sSH[e*4+1+i] + sV1[e*48 + r])*RFANf;
    }
  }
}

__global__ void k_ex(const int* __restrict__ ei, int E){
  int t = blockIdx.x*blockDim.x+threadIdx.x;
  if (t >= E*4) return;
  int e = t >> 2, h = t & 3;
  int dst = ei[E + e];
  float ex = expf(d_logits[t] - d_segmax[dst*4+h]);
  d_exb[t] = ex;
  atomicAdd(d_denom + dst*4 + h, ex);
}

__global__ void k_agg(const int* __restrict__ ei, int E){
  int t = blockIdx.x*blockDim.x+threadIdx.x;
  if (t >= E*80) return;
  int e = t/80, r = t - e*80;
  int dst = ei[E + e];
  if (r < 32){
    int h = r >> 3;
    float alpha = d_exb[e*4+h]/(d_denom[dst*4+h] + 1e-12f);
    atomicAdd(d_agg0 + dst*32 + r, alpha*d_v0e[(size_t)e*32 + r]);
  } else {
    int r2 = r - 32, h = r2/12;
    float alpha = d_exb[e*4+h]/(d_denom[dst*4+h] + 1e-12f);
    atomicAdd(d_agg1 + dst*48 + r2, alpha*d_v1e[(size_t)e*48 + r2]);
  }
}

__global__ void k_node(const float* __restrict__ nf,
    const float* __restrict__ Wo0, const float* __restrict__ Wo1,
    const float* __restrict__ Wf10, const float* __restrict__ Wf11,
    const float* __restrict__ Wf20, const float* __restrict__ Wf21,
    float* __restrict__ out, int N)
{
  __shared__ float sx0[32], sx1[48], sa0[64], sa1[48];
  int n = blockIdx.x, t = threadIdx.x;
  if (t < 32){
    float acc = 0.f;
#pragma unroll
    for (int u = 0; u < 32; u++) acc += d_agg0[n*32+u]*Wo0[u*32+t];
    sx0[t] = nf[(size_t)n*80 + t] + acc*RS32f;
  } else if (t < 80){
    int r = t-32, w = r/3, i = r - w*3;
    float acc = 0.f;
#pragma unroll
    for (int u = 0; u < 16; u++) acc += d_agg1[n*48+u*3+i]*Wo1[u*16+w];
    sx1[r] = nf[(size_t)n*80 + 32 + r] + acc*0.25f;
  }
  __syncthreads();
  if (t < 64){
    float acc = 0.f;
#pragma unroll
    for (int u = 0; u < 32; u++) acc += sx0[u]*Wf10[u*64+t];
    float a = acc*RS32f;
    sa0[t] = a/(1.f+expf(-a));
  } else if (t < 112){
    int r = t-64, w = r/3, i = r - w*3;
    float acc = 0.f;
#pragma unroll
    for (int u = 0; u < 16; u++) acc += sx1[u*3+i]*Wf11[u*16+w];
    sa1[r] = acc*0.25f;
  }
  __syncthreads();
  if (t < 16){
    float x = sa1[t*3], y = sa1[t*3+1], z = sa1[t*3+2];
    float nm = sqrtf(x*x+y*y+z*z);
    float g = (nm < 1e-8f) ? 0.f : (nm/(1.f+expf(-nm)))/nm;
    sa1[t*3] = x*g; sa1[t*3+1] = y*g; sa1[t*3+2] = z*g;
  }
  __syncthreads();
  if (t < 32){
    float acc = 0.f;
#pragma unroll
    for (int u = 0; u < 64; u++) acc += sa0[u]*Wf20[u*32+t];
    out[(size_t)n*80 + t] = sx0[t] + acc*0.125f;
  } else if (t < 80){
    int r = t-32, w = r/3, i = r - w*3;
    float acc = 0.f;
#pragma unroll
    for (int u = 0; u < 16; u++) acc += sa1[u*3+i]*Wf21[u*16+w];
    out[(size_t)n*80 + t] = sx1[r] + acc*0.25f;
  }
}

extern "C" void kernel_launch(void* const* d_in, const int* in_sizes, int n_in,
                              void* d_out, int out_size){
  const float* nf   = (const float*)d_in[0];
  const int*   ei   = (const int*)  d_in[1];
  const float* esh  = (const float*)d_in[2];
  const float* emb  = (const float*)d_in[3];
  const float* Wq0  = (const float*)d_in[4];
  const float* Wq1  = (const float*)d_in[5];
  const float* Wk1  = (const float*)d_in[6];
  const float* bk1  = (const float*)d_in[7];
  const float* Wk2  = (const float*)d_in[8];
  const float* bk2  = (const float*)d_in[9];
  const float* Wv1  = (const float*)d_in[10];
  const float* bv1  = (const float*)d_in[11];
  const float* Wv2  = (const float*)d_in[12];
  const float* bv2  = (const float*)d_in[13];
  const float* Wd0  = (const float*)d_in[14];
  const float* Wd1  = (const float*)d_in[15];
  const float* Wo0  = (const float*)d_in[16];
  const float* Wo1  = (const float*)d_in[17];
  const float* Wf10 = (const float*)d_in[18];
  const float* Wf11 = (const float*)d_in[19];
  const float* Wf20 = (const float*)d_in[20];
  const float* Wf21 = (const float*)d_in[21];
  float* out = (float*)d_out;

  int N = in_sizes[0]/80;
  int E = in_sizes[1]/2;

  static int smCount = 0;
  if (!smCount){
    cudaFuncSetAttribute(k_edge, cudaFuncAttributeMaxDynamicSharedMemorySize, SMEM_BYTES);
    cudaDeviceGetAttribute(&smCount, cudaDevAttrMultiProcessorCount, 0);
    if (smCount <= 0) smCount = 148;
  }
  int nT = (E + 31)/32;
  int grid = nT < 3*smCount ? nT : 3*smCount;

  k_prep<<<(2*32*2304+255)/256, 256>>>(Wk2, Wv2);
  k_init<<<(N*48+255)/256, 256>>>(N);
  k_q<<<(N*80+255)/256, 256>>>(nf, Wq0, Wq1, N);
  k_edge<<<grid, 256, SMEM_BYTES>>>(nf, ei, esh, emb,
      Wk1, bk1, bk2, Wv1, bv1, bv2, Wd0, Wd1, N, E);
  k_ex<<<(E*4+255)/256, 256>>>(ei, E);
  k_agg<<<(E*80+255)/256, 256>>>(ei, E);
  k_node<<<N, 128>>>(nf, Wo0, Wo1, Wf10, Wf11, Wf20, Wf21, out, N);
}